// round 1
// baseline (speedup 1.0000x reference)
#include <cuda_runtime.h>

#define NN 20000
#define EE 320000
#define EA 340000      // E + N self loops
#define HIDD 768
#define NH 8
#define NC 96
#define NL 16
#define NGB 16
#define EMB 512

// ---------------- scratch (device globals; no allocations) ----------------
__device__ float d_h[NN * HIDD];      // node features (updated in place per layer)
__device__ float d_g[NN * HIDD];      // g = h @ W
__device__ float d_as[NN * NH];
__device__ float d_ad[NN * NH];
__device__ float d_e[EA * NH];        // per-edge logits -> probs
__device__ int   d_deg[NN];
__device__ int   d_rowptr[NN + 1];
__device__ int   d_cursor[NN];
__device__ int   d_csrsrc[EA];
__device__ int   d_gstart[NGB + 1];
__device__ float d_pool[NGB * HIDD];

// ---------------- CSR build ----------------
__global__ void k_zero_deg() {
    int i = blockIdx.x * 256 + threadIdx.x;
    if (i < NN) d_deg[i] = 0;
}

__global__ void k_hist(const int* __restrict__ ei) {
    int i = blockIdx.x * 256 + threadIdx.x;
    if (i >= EA) return;
    int dst = (i < EE) ? ei[EE + i] : (i - EE);
    atomicAdd(&d_deg[dst], 1);
}

__global__ void k_scan() {
    __shared__ int sdata[1024];
    __shared__ int carry;
    int tid = threadIdx.x;
    if (tid == 0) { carry = 0; d_rowptr[0] = 0; }
    __syncthreads();
    for (int base = 0; base < NN; base += 1024) {
        int i = base + tid;
        int v = (i < NN) ? d_deg[i] : 0;
        sdata[tid] = v;
        __syncthreads();
        for (int off = 1; off < 1024; off <<= 1) {
            int t = (tid >= off) ? sdata[tid - off] : 0;
            __syncthreads();
            sdata[tid] += t;
            __syncthreads();
        }
        int incl = sdata[tid] + carry;
        if (i < NN) d_rowptr[i + 1] = incl;
        __syncthreads();
        if (tid == 1023) carry = incl;
        __syncthreads();
    }
    for (int i = tid; i < NN; i += 1024) d_cursor[i] = d_rowptr[i];
}

__global__ void k_scatter(const int* __restrict__ ei) {
    int i = blockIdx.x * 256 + threadIdx.x;
    if (i >= EA) return;
    int src, dst;
    if (i < EE) { src = ei[i]; dst = ei[EE + i]; }
    else        { src = i - EE; dst = src; }
    int slot = atomicAdd(&d_cursor[dst], 1);
    d_csrsrc[slot] = src;
}

// ---------------- graph boundaries for pooling (batch is sorted) ----------------
__global__ void k_gstart(const int* __restrict__ batch) {
    int n = blockIdx.x * 256 + threadIdx.x;
    if (n >= NN) return;
    int b = batch[n];
    if (n == 0) {
        for (int bb = 0; bb <= b; bb++) d_gstart[bb] = 0;
    } else {
        int pb = batch[n - 1];
        if (pb != b) for (int bb = pb + 1; bb <= b; bb++) d_gstart[bb] = n;
    }
    if (n == NN - 1) {
        for (int bb = b + 1; bb <= NGB; bb++) d_gstart[bb] = NN;
    }
}

// ---------------- input projection: h = x @ proj_W + proj_b ----------------
__global__ void k_proj(const float* __restrict__ x, const float* __restrict__ W,
                       const float* __restrict__ b) {
    int id = blockIdx.x * 256 + threadIdx.x;
    if (id >= NN * HIDD) return;
    int n = id / HIDD, j = id % HIDD;
    float s = b[j];
#pragma unroll
    for (int f = 0; f < 5; f++) s += x[n * 5 + f] * W[f * HIDD + j];
    d_h[id] = s;
}

// ---------------- SGEMM: d_g = d_h (M x 768) @ B (768 x 768) ----------------
__global__ __launch_bounds__(256) void k_gemm(const float* __restrict__ B) {
    const int K = HIDD, Nd = HIDD, M = NN;
    __shared__ float As[8][128];
    __shared__ float Bs[8][128];
    int tid  = threadIdx.x;
    int brow = blockIdx.y * 128, bcol = blockIdx.x * 128;
    int tx   = (tid % 16) * 8;
    int ty   = (tid / 16) * 8;
    float acc[8][8];
#pragma unroll
    for (int i = 0; i < 8; i++)
#pragma unroll
        for (int j = 0; j < 8; j++) acc[i][j] = 0.f;

    int aRow = tid >> 1, aCol = (tid & 1) * 4;
    int bRow = tid >> 5, bCol = (tid & 31) * 4;

    for (int k0 = 0; k0 < K; k0 += 8) {
        float4 av = make_float4(0.f, 0.f, 0.f, 0.f);
        int gr = brow + aRow;
        if (gr < M) av = *(const float4*)&d_h[(size_t)gr * K + k0 + aCol];
        As[aCol + 0][aRow] = av.x;
        As[aCol + 1][aRow] = av.y;
        As[aCol + 2][aRow] = av.z;
        As[aCol + 3][aRow] = av.w;
        *(float4*)&Bs[bRow][bCol] =
            *(const float4*)&B[(size_t)(k0 + bRow) * Nd + bcol + bCol];
        __syncthreads();
#pragma unroll
        for (int k = 0; k < 8; k++) {
            float4 a0 = *(float4*)&As[k][ty];
            float4 a1 = *(float4*)&As[k][ty + 4];
            float4 b0 = *(float4*)&Bs[k][tx];
            float4 b1 = *(float4*)&Bs[k][tx + 4];
            float ar[8] = {a0.x, a0.y, a0.z, a0.w, a1.x, a1.y, a1.z, a1.w};
            float br[8] = {b0.x, b0.y, b0.z, b0.w, b1.x, b1.y, b1.z, b1.w};
#pragma unroll
            for (int i = 0; i < 8; i++)
#pragma unroll
                for (int j = 0; j < 8; j++) acc[i][j] += ar[i] * br[j];
        }
        __syncthreads();
    }
#pragma unroll
    for (int i = 0; i < 8; i++) {
        int gr = brow + ty + i;
        if (gr < M) {
#pragma unroll
            for (int j = 0; j < 8; j += 4) {
                *(float4*)&d_g[(size_t)gr * Nd + bcol + tx + j] =
                    make_float4(acc[i][j], acc[i][j + 1], acc[i][j + 2], acc[i][j + 3]);
            }
        }
    }
}

// ---------------- attention coefficients a_s, a_d ----------------
__global__ void k_asd(const float* __restrict__ att_s, const float* __restrict__ att_d) {
    int id = blockIdx.x * 256 + threadIdx.x;
    if (id >= NN * NH) return;
    int h = id & 7;
    const float* gr = d_g + (size_t)(id >> 3) * HIDD + h * NC;
    const float* vs = att_s + h * NC;
    const float* vd = att_d + h * NC;
    float s1 = 0.f, s2 = 0.f;
#pragma unroll 8
    for (int c = 0; c < NC; c++) {
        float gv = gr[c];
        s1 += gv * vs[c];
        s2 += gv * vd[c];
    }
    d_as[id] = s1;
    d_ad[id] = s2;
}

// ---------------- per-node softmax + aggregate (1 warp / dst node) ----------------
__global__ __launch_bounds__(256) void k_attn(const float* __restrict__ bias) {
    int warp = threadIdx.x >> 5, lane = threadIdx.x & 31;
    int n = blockIdx.x * 8 + warp;  // grid = 2500 -> covers exactly 20000
    __shared__ float s_inv[8][8];
    __shared__ float s_alpha[8][8];

    int beg = d_rowptr[n], end = d_rowptr[n + 1];
    float ad[8];
#pragma unroll
    for (int h = 0; h < 8; h++) ad[h] = d_ad[n * 8 + h];

    // pass 1: logits + max
    float mx[8];
#pragma unroll
    for (int h = 0; h < 8; h++) mx[h] = -1e30f;
    for (int i0 = beg; i0 < end; i0 += 32) {
        int idx = i0 + lane;
        bool v = idx < end;
        int s = v ? d_csrsrc[idx] : 0;
#pragma unroll
        for (int h = 0; h < 8; h++) {
            float e = -1e30f;
            if (v) {
                e = d_as[s * 8 + h] + ad[h];
                e = e > 0.f ? e : 0.2f * e;
                d_e[(size_t)idx * 8 + h] = e;
            }
            mx[h] = fmaxf(mx[h], e);
        }
    }
#pragma unroll
    for (int h = 0; h < 8; h++)
        for (int off = 16; off; off >>= 1)
            mx[h] = fmaxf(mx[h], __shfl_xor_sync(0xffffffffu, mx[h], off));

    // pass 2: exp + sum
    float sm[8];
#pragma unroll
    for (int h = 0; h < 8; h++) sm[h] = 0.f;
    for (int i0 = beg; i0 < end; i0 += 32) {
        int idx = i0 + lane;
        bool v = idx < end;
#pragma unroll
        for (int h = 0; h < 8; h++) {
            if (v) {
                float p = __expf(d_e[(size_t)idx * 8 + h] - mx[h]);
                d_e[(size_t)idx * 8 + h] = p;
                sm[h] += p;
            }
        }
    }
#pragma unroll
    for (int h = 0; h < 8; h++)
        for (int off = 16; off; off >>= 1)
            sm[h] += __shfl_xor_sync(0xffffffffu, sm[h], off);
    if (lane == 0) {
#pragma unroll
        for (int h = 0; h < 8; h++) s_inv[warp][h] = 1.f / (sm[h] + 1e-16f);
    }
    __threadfence_block();
    __syncwarp();

    // pass 3: weighted gather-accumulate of g rows
    float acc[24];
#pragma unroll
    for (int t = 0; t < 24; t++) acc[t] = 0.f;
    for (int idx = beg; idx < end; idx++) {
        int s = d_csrsrc[idx];
        if (lane < 8) s_alpha[warp][lane] = d_e[(size_t)idx * 8 + lane] * s_inv[warp][lane];
        __syncwarp();
        const float* grow = d_g + (size_t)s * HIDD;
#pragma unroll
        for (int t = 0; t < 24; t++) {
            int j = lane + 32 * t;
            acc[t] += s_alpha[warp][j / 96] * grow[j];
        }
        __syncwarp();
    }
#pragma unroll
    for (int t = 0; t < 24; t++) {
        int j = lane + 32 * t;
        float v = acc[t] + bias[j];
        d_h[(size_t)n * HIDD + j] = v > 0.f ? v : 0.f;
    }
}

// ---------------- mean pooling per graph ----------------
__global__ void k_pool() {
    int b = blockIdx.x;
    int j = blockIdx.y * 256 + threadIdx.x;
    int beg = d_gstart[b], end = d_gstart[b + 1];
    float s = 0.f;
    for (int n = beg; n < end; n++) s += d_h[(size_t)n * HIDD + j];
    float cnt = (float)(end - beg);
    d_pool[b * HIDD + j] = s / fmaxf(cnt, 1.0f);
}

// ---------------- final fc ----------------
__global__ void k_fc(const float* __restrict__ W, const float* __restrict__ b,
                     float* __restrict__ out) {
    int id = blockIdx.x * 256 + threadIdx.x;
    if (id >= NGB * EMB) return;
    int bb = id / EMB, k = id % EMB;
    float s = b[k];
    for (int j = 0; j < HIDD; j++) s += d_pool[bb * HIDD + j] * W[j * EMB + k];
    out[id] = s;
}

// ---------------- launch ----------------
extern "C" void kernel_launch(void* const* d_in, const int* in_sizes, int n_in,
                              void* d_out, int out_size) {
    const float* x     = (const float*)d_in[0];
    const int*   ei    = (const int*)d_in[1];
    const int*   batch = (const int*)d_in[2];
    const float* projW = (const float*)d_in[3];
    const float* projb = (const float*)d_in[4];
    const float* convW = (const float*)d_in[5];
    const float* attS  = (const float*)d_in[6];
    const float* attD  = (const float*)d_in[7];
    const float* convb = (const float*)d_in[8];
    const float* fcW   = (const float*)d_in[9];
    const float* fcb   = (const float*)d_in[10];
    float* out = (float*)d_out;

    k_zero_deg<<<(NN + 255) / 256, 256>>>();
    k_hist<<<(EA + 255) / 256, 256>>>(ei);
    k_scan<<<1, 1024>>>();
    k_scatter<<<(EA + 255) / 256, 256>>>(ei);
    k_gstart<<<(NN + 255) / 256, 256>>>(batch);
    k_proj<<<(NN * HIDD + 255) / 256, 256>>>(x, projW, projb);

    for (int l = 0; l < NL; l++) {
        dim3 gg(6, 157);  // 768/128 x ceil(20000/128)
        k_gemm<<<gg, 256>>>(convW + (size_t)l * HIDD * HIDD);
        k_asd<<<(NN * NH + 255) / 256, 256>>>(attS + l * HIDD, attD + l * HIDD);
        k_attn<<<NN / 8, 256>>>(convb + l * HIDD);
    }

    dim3 gp(NGB, 3);
    k_pool<<<gp, 256>>>();
    k_fc<<<(NGB * EMB + 255) / 256, 256>>>(fcW, fcb, out);
}

// round 4
// speedup vs baseline: 1.6133x; 1.6133x over previous
#include <cuda_runtime.h>
#include <cuda_bf16.h>
#include <cstdint>

#define NN 20000
#define EE 320000
#define EA 340000      // E + N self loops
#define HIDD 768
#define NH 8
#define NC 96
#define NL 16
#define NGB 16
#define EMB 512
#define KCAT 2304      // 3 * HIDD (bf16 split: hi*hi + lo*hi + hi*lo)

// ---------------- scratch (device globals; no allocations) ----------------
__device__ float d_h[NN * HIDD];
__device__ float d_g[NN * HIDD];
__device__ float d_as[NN * NH];
__device__ float d_ad[NN * NH];
__device__ float d_e[EA * NH];
__device__ int   d_deg[NN];
__device__ int   d_rowptr[NN + 1];
__device__ int   d_cursor[NN];
__device__ int   d_csrsrc[EA];
__device__ int   d_gstart[NGB + 1];
__device__ float d_pool[NGB * HIDD];
__device__ __nv_bfloat16 d_Acat[(size_t)NN * KCAT];           // h split, [N, 2304]
__device__ __nv_bfloat16 d_WcatT[(size_t)NL * HIDD * KCAT];   // W^T split, [L, 768n, 2304k]

// ---------------- CSR build ----------------
__global__ void k_zero_deg() {
    int i = blockIdx.x * 256 + threadIdx.x;
    if (i < NN) d_deg[i] = 0;
}

__global__ void k_hist(const int* __restrict__ ei) {
    int i = blockIdx.x * 256 + threadIdx.x;
    if (i >= EA) return;
    int dst = (i < EE) ? ei[EE + i] : (i - EE);
    atomicAdd(&d_deg[dst], 1);
}

__global__ void k_scan() {
    __shared__ int sdata[1024];
    __shared__ int carry;
    int tid = threadIdx.x;
    if (tid == 0) { carry = 0; d_rowptr[0] = 0; }
    __syncthreads();
    for (int base = 0; base < NN; base += 1024) {
        int i = base + tid;
        int v = (i < NN) ? d_deg[i] : 0;
        sdata[tid] = v;
        __syncthreads();
        for (int off = 1; off < 1024; off <<= 1) {
            int t = (tid >= off) ? sdata[tid - off] : 0;
            __syncthreads();
            sdata[tid] += t;
            __syncthreads();
        }
        int incl = sdata[tid] + carry;
        if (i < NN) d_rowptr[i + 1] = incl;
        __syncthreads();
        if (tid == 1023) carry = incl;
        __syncthreads();
    }
    for (int i = tid; i < NN; i += 1024) d_cursor[i] = d_rowptr[i];
}

__global__ void k_scatter(const int* __restrict__ ei) {
    int i = blockIdx.x * 256 + threadIdx.x;
    if (i >= EA) return;
    int src, dst;
    if (i < EE) { src = ei[i]; dst = ei[EE + i]; }
    else        { src = i - EE; dst = src; }
    int slot = atomicAdd(&d_cursor[dst], 1);
    d_csrsrc[slot] = src;
}

__global__ void k_gstart(const int* __restrict__ batch) {
    int n = blockIdx.x * 256 + threadIdx.x;
    if (n >= NN) return;
    int b = batch[n];
    if (n == 0) {
        for (int bb = 0; bb <= b; bb++) d_gstart[bb] = 0;
    } else {
        int pb = batch[n - 1];
        if (pb != b) for (int bb = pb + 1; bb <= b; bb++) d_gstart[bb] = n;
    }
    if (n == NN - 1) {
        for (int bb = b + 1; bb <= NGB; bb++) d_gstart[bb] = NN;
    }
}

// ---------------- input projection ----------------
__global__ void k_proj(const float* __restrict__ x, const float* __restrict__ W,
                       const float* __restrict__ b) {
    int id = blockIdx.x * 256 + threadIdx.x;
    if (id >= NN * HIDD) return;
    int n = id / HIDD, j = id % HIDD;
    float s = b[j];
#pragma unroll
    for (int f = 0; f < 5; f++) s += x[n * 5 + f] * W[f * HIDD + j];
    d_h[id] = s;
}

// ---------------- bf16 split: weights (once) ----------------
__global__ void k_split_w(const float* __restrict__ convW) {
    int id = blockIdx.x * 256 + threadIdx.x;
    if (id >= NL * HIDD * HIDD) return;
    int l = id / (HIDD * HIDD);
    int rem = id % (HIDD * HIDD);
    int k = rem / HIDD, n = rem % HIDD;
    float v = convW[id];
    __nv_bfloat16 hi = __float2bfloat16(v);
    __nv_bfloat16 lo = __float2bfloat16(v - __bfloat162float(hi));
    size_t base = ((size_t)l * HIDD + n) * KCAT;
    d_WcatT[base + k]            = hi;   // pairs with h_hi
    d_WcatT[base + HIDD + k]     = hi;   // pairs with h_lo
    d_WcatT[base + 2 * HIDD + k] = lo;   // pairs with h_hi
}

// ---------------- bf16 split: h (per layer) ----------------
__global__ void k_split_h() {
    int id = blockIdx.x * 256 + threadIdx.x;
    if (id >= NN * HIDD) return;
    int n = id / HIDD, k = id % HIDD;
    float v = d_h[id];
    __nv_bfloat16 hi = __float2bfloat16(v);
    __nv_bfloat16 lo = __float2bfloat16(v - __bfloat162float(hi));
    size_t base = (size_t)n * KCAT;
    d_Acat[base + k]            = hi;
    d_Acat[base + HIDD + k]     = lo;
    d_Acat[base + 2 * HIDD + k] = hi;
}

// =====================================================================
// HMMA GEMM: d_g[m,n] = sum_k Acat[m,k] * WcatT[l][n,k]
// block tile 128x128, BK=64, 3-stage cp.async, mma.sync.m16n8k16.bf16
// =====================================================================
#define BK 64
#define STAGES 3
#define STG_A 16384                       // 128 rows x 128 bytes
#define STG_B 16384
#define SMEM_GEMM (STAGES * (STG_A + STG_B))   // 98304

__device__ __forceinline__ uint32_t swz(uint32_t b) { return b ^ ((b >> 3) & 0x70); }

__device__ __forceinline__ uint32_t smem_u32(const void* p) {
    uint32_t a;
    asm("{ .reg .u64 t; cvta.to.shared.u64 t, %1; cvt.u32.u64 %0, t; }" : "=r"(a) : "l"(p));
    return a;
}

#define CP_ASYNC(dst, src, sz) \
    asm volatile("cp.async.cg.shared.global [%0], [%1], 16, %2;" \
        :: "r"(dst), "l"(src), "r"(sz))
#define CP_COMMIT() asm volatile("cp.async.commit_group;")
#define CP_WAIT1()  asm volatile("cp.async.wait_group 1;")

#define LDMX4(r0, r1, r2, r3, a) \
    asm volatile("ldmatrix.sync.aligned.m8n8.x4.shared.b16 {%0,%1,%2,%3}, [%4];" \
        : "=r"(r0), "=r"(r1), "=r"(r2), "=r"(r3) : "r"(a))

#define MMA16816(d, a, b) \
    asm volatile("mma.sync.aligned.m16n8k16.row.col.f32.bf16.bf16.f32 " \
        "{%0,%1,%2,%3}, {%4,%5,%6,%7}, {%8,%9}, {%0,%1,%2,%3};" \
        : "+f"((d)[0]), "+f"((d)[1]), "+f"((d)[2]), "+f"((d)[3]) \
        : "r"((a)[0]), "r"((a)[1]), "r"((a)[2]), "r"((a)[3]), "r"((b)[0]), "r"((b)[1]))

__global__ __launch_bounds__(256, 1) void k_gemm_hmma(const __nv_bfloat16* __restrict__ Wl) {
    extern __shared__ __align__(128) char smem[];
    uint32_t sA = smem_u32(smem);                    // STAGES x 16KB
    uint32_t sB = sA + STAGES * STG_A;               // STAGES x 16KB

    const int tid = threadIdx.x;
    const int lane = tid & 31, warp = tid >> 5;
    const int wm = warp & 3, wn = warp >> 2;         // 4 m-warps x 2 n-warps
    const int mtile = blockIdx.y, ntile = blockIdx.x;
    const int mbase = mtile * 128;

    const __nv_bfloat16* Ag = d_Acat;

    // per-thread cp.async coords: 8 chunks of 16B per stage (4 A + 4 B)
    // chunk id = it*256 + tid in [0,1024): row=id/8, ck=id%8
    auto issue_stage = [&](int kt, int st) {
        uint32_t a_dst = sA + st * STG_A;
        uint32_t b_dst = sB + st * STG_B;
        int k0 = kt * BK;
#pragma unroll
        for (int it = 0; it < 4; it++) {
            int id = it * 256 + tid;
            int row = id >> 3, ck = id & 7;
            // A
            int gr = mbase + row;
            const __nv_bfloat16* srcA = Ag + (size_t)gr * KCAT + k0 + ck * 8;
            int szA = (gr < NN) ? 16 : 0;
            CP_ASYNC(a_dst + swz(row * 128 + ck * 16), srcA, szA);
            // B (always in bounds: ntile*128+row < 768)
            const __nv_bfloat16* srcB = Wl + (size_t)(ntile * 128 + row) * KCAT + k0 + ck * 8;
            CP_ASYNC(b_dst + swz(row * 128 + ck * 16), srcB, 16);
        }
        CP_COMMIT();
    };

    issue_stage(0, 0);
    issue_stage(1, 1);

    float acc[2][8][4];
#pragma unroll
    for (int i = 0; i < 2; i++)
#pragma unroll
        for (int j = 0; j < 8; j++)
#pragma unroll
            for (int c = 0; c < 4; c++) acc[i][j][c] = 0.f;

    const int NKT = KCAT / BK;   // 36
    for (int kt = 0; kt < NKT; kt++) {
        CP_WAIT1();
        __syncthreads();
        if (kt + 2 < NKT) issue_stage(kt + 2, (kt + 2) % STAGES);
        else CP_COMMIT();

        int st = kt % STAGES;
        uint32_t aS = sA + st * STG_A;
        uint32_t bS = sB + st * STG_B;

#pragma unroll
        for (int ks = 0; ks < 4; ks++) {          // k16 steps within BK
            uint32_t afr[2][4];
#pragma unroll
            for (int im = 0; im < 2; im++) {
                int row = wm * 32 + im * 16 + (lane & 15);
                int kk = ks * 16 + (lane >> 4) * 8;
                LDMX4(afr[im][0], afr[im][1], afr[im][2], afr[im][3],
                      aS + swz(row * 128 + kk * 2));
            }
            uint32_t bfr[8][2];
#pragma unroll
            for (int pr = 0; pr < 4; pr++) {      // each x4 covers two n8 frags
                int nrow = wn * 64 + pr * 16 + (lane & 7) + ((lane & 16) ? 8 : 0);
                int kk = ks * 16 + ((lane & 8) ? 8 : 0);
                uint32_t r0, r1, r2, r3;
                LDMX4(r0, r1, r2, r3, bS + swz(nrow * 128 + kk * 2));
                bfr[pr * 2][0] = r0;     bfr[pr * 2][1] = r1;
                bfr[pr * 2 + 1][0] = r2; bfr[pr * 2 + 1][1] = r3;
            }
#pragma unroll
            for (int im = 0; im < 2; im++)
#pragma unroll
                for (int jn = 0; jn < 8; jn++)
                    MMA16816(acc[im][jn], afr[im], bfr[jn]);
        }
        __syncthreads();
    }

    // epilogue: acc thread mapping: d0,d1 -> (row = m0+lane/4, col = n0+(lane%4)*2), d2,d3 -> row+8
#pragma unroll
    for (int im = 0; im < 2; im++) {
        int r0 = mbase + wm * 32 + im * 16 + (lane >> 2);
#pragma unroll
        for (int jn = 0; jn < 8; jn++) {
            int col = ntile * 128 + wn * 64 + jn * 8 + (lane & 3) * 2;
            if (r0 < NN)
                *(float2*)&d_g[(size_t)r0 * HIDD + col] = make_float2(acc[im][jn][0], acc[im][jn][1]);
            if (r0 + 8 < NN)
                *(float2*)&d_g[(size_t)(r0 + 8) * HIDD + col] = make_float2(acc[im][jn][2], acc[im][jn][3]);
        }
    }
}

// ---------------- attention coefficients ----------------
__global__ void k_asd(const float* __restrict__ att_s, const float* __restrict__ att_d) {
    int id = blockIdx.x * 256 + threadIdx.x;
    if (id >= NN * NH) return;
    int h = id & 7;
    const float* gr = d_g + (size_t)(id >> 3) * HIDD + h * NC;
    const float* vs = att_s + h * NC;
    const float* vd = att_d + h * NC;
    float s1 = 0.f, s2 = 0.f;
#pragma unroll 8
    for (int c = 0; c < NC; c++) {
        float gv = gr[c];
        s1 += gv * vs[c];
        s2 += gv * vd[c];
    }
    d_as[id] = s1;
    d_ad[id] = s2;
}

// ---------------- per-node softmax + aggregate ----------------
__global__ __launch_bounds__(256) void k_attn(const float* __restrict__ bias) {
    int warp = threadIdx.x >> 5, lane = threadIdx.x & 31;
    int n = blockIdx.x * 8 + warp;
    __shared__ float s_inv[8][8];
    __shared__ float s_alpha[8][8];

    int beg = d_rowptr[n], end = d_rowptr[n + 1];
    float ad[8];
#pragma unroll
    for (int h = 0; h < 8; h++) ad[h] = d_ad[n * 8 + h];

    float mx[8];
#pragma unroll
    for (int h = 0; h < 8; h++) mx[h] = -1e30f;
    for (int i0 = beg; i0 < end; i0 += 32) {
        int idx = i0 + lane;
        bool v = idx < end;
        int s = v ? d_csrsrc[idx] : 0;
#pragma unroll
        for (int h = 0; h < 8; h++) {
            float e = -1e30f;
            if (v) {
                e = d_as[s * 8 + h] + ad[h];
                e = e > 0.f ? e : 0.2f * e;
                d_e[(size_t)idx * 8 + h] = e;
            }
            mx[h] = fmaxf(mx[h], e);
        }
    }
#pragma unroll
    for (int h = 0; h < 8; h++)
        for (int off = 16; off; off >>= 1)
            mx[h] = fmaxf(mx[h], __shfl_xor_sync(0xffffffffu, mx[h], off));

    float sm[8];
#pragma unroll
    for (int h = 0; h < 8; h++) sm[h] = 0.f;
    for (int i0 = beg; i0 < end; i0 += 32) {
        int idx = i0 + lane;
        bool v = idx < end;
#pragma unroll
        for (int h = 0; h < 8; h++) {
            if (v) {
                float p = __expf(d_e[(size_t)idx * 8 + h] - mx[h]);
                d_e[(size_t)idx * 8 + h] = p;
                sm[h] += p;
            }
        }
    }
#pragma unroll
    for (int h = 0; h < 8; h++)
        for (int off = 16; off; off >>= 1)
            sm[h] += __shfl_xor_sync(0xffffffffu, sm[h], off);
    if (lane == 0) {
#pragma unroll
        for (int h = 0; h < 8; h++) s_inv[warp][h] = 1.f / (sm[h] + 1e-16f);
    }
    __syncwarp();

    float acc[24];
#pragma unroll
    for (int t = 0; t < 24; t++) acc[t] = 0.f;
    for (int idx = beg; idx < end; idx++) {
        int s = d_csrsrc[idx];
        if (lane < 8) s_alpha[warp][lane] = d_e[(size_t)idx * 8 + lane] * s_inv[warp][lane];
        __syncwarp();
        const float* grow = d_g + (size_t)s * HIDD;
#pragma unroll
        for (int t = 0; t < 24; t++) {
            int j = lane + 32 * t;
            acc[t] += s_alpha[warp][j / 96] * grow[j];
        }
        __syncwarp();
    }
#pragma unroll
    for (int t = 0; t < 24; t++) {
        int j = lane + 32 * t;
        float v = acc[t] + bias[j];
        d_h[(size_t)n * HIDD + j] = v > 0.f ? v : 0.f;
    }
}

// ---------------- pooling / fc ----------------
__global__ void k_pool() {
    int b = blockIdx.x;
    int j = blockIdx.y * 256 + threadIdx.x;
    int beg = d_gstart[b], end = d_gstart[b + 1];
    float s = 0.f;
    for (int n = beg; n < end; n++) s += d_h[(size_t)n * HIDD + j];
    float cnt = (float)(end - beg);
    d_pool[b * HIDD + j] = s / fmaxf(cnt, 1.0f);
}

__global__ void k_fc(const float* __restrict__ W, const float* __restrict__ b,
                     float* __restrict__ out) {
    int id = blockIdx.x * 256 + threadIdx.x;
    if (id >= NGB * EMB) return;
    int bb = id / EMB, k = id % EMB;
    float s = b[k];
    for (int j = 0; j < HIDD; j++) s += d_pool[bb * HIDD + j] * W[j * EMB + k];
    out[id] = s;
}

// ---------------- host launch ----------------
extern "C" void kernel_launch(void* const* d_in, const int* in_sizes, int n_in,
                              void* d_out, int out_size) {
    const float* x     = (const float*)d_in[0];
    const int*   ei    = (const int*)d_in[1];
    const int*   batch = (const int*)d_in[2];
    const float* projW = (const float*)d_in[3];
    const float* projb = (const float*)d_in[4];
    const float* convW = (const float*)d_in[5];
    const float* attS  = (const float*)d_in[6];
    const float* attD  = (const float*)d_in[7];
    const float* convb = (const float*)d_in[8];
    const float* fcW   = (const float*)d_in[9];
    const float* fcb   = (const float*)d_in[10];
    float* out = (float*)d_out;

    static bool attr_set = false;
    if (!attr_set) {
        cudaFuncSetAttribute(k_gemm_hmma, cudaFuncAttributeMaxDynamicSharedMemorySize, SMEM_GEMM);
        attr_set = true;
    }

    void* pW = nullptr;
    cudaGetSymbolAddress(&pW, d_WcatT);
    const __nv_bfloat16* Wcat = (const __nv_bfloat16*)pW;

    k_zero_deg<<<(NN + 255) / 256, 256>>>();
    k_hist<<<(EA + 255) / 256, 256>>>(ei);
    k_scan<<<1, 1024>>>();
    k_scatter<<<(EA + 255) / 256, 256>>>(ei);
    k_gstart<<<(NN + 255) / 256, 256>>>(batch);
    k_proj<<<(NN * HIDD + 255) / 256, 256>>>(x, projW, projb);
    k_split_w<<<(NL * HIDD * HIDD + 255) / 256, 256>>>(convW);

    for (int l = 0; l < NL; l++) {
        k_split_h<<<(NN * HIDD + 255) / 256, 256>>>();
        dim3 gg(HIDD / 128, (NN + 127) / 128);   // 6 x 157
        k_gemm_hmma<<<gg, 256, SMEM_GEMM>>>(Wcat + (size_t)l * HIDD * KCAT);
        k_asd<<<(NN * NH + 255) / 256, 256>>>(attS + l * HIDD, attD + l * HIDD);
        k_attn<<<NN / 8, 256>>>(convb + l * HIDD);
    }

    dim3 gp(NGB, 3);
    k_pool<<<gp, 256>>>();
    k_fc<<<(NGB * EMB + 255) / 256, 256>>>(fcW, fcb, out);
}

// round 5
// speedup vs baseline: 1.6764x; 1.0391x over previous
#include <cuda_runtime.h>
#include <cuda_bf16.h>
#include <cstdint>

#define NN 20000
#define EE 320000
#define EA 340000      // E + N self loops
#define HIDD 768
#define NH 8
#define NC 96
#define NL 16
#define NGB 16
#define EMB 512
#define KCAT 2304      // 3 * HIDD (bf16 split: hi*hi + lo*hi + hi*lo)

// ---------------- scratch (device globals; no allocations) ----------------
__device__ float d_h[NN * HIDD];
__device__ float d_g[NN * HIDD];
__device__ float d_as[NN * NH];
__device__ float d_ad[NN * NH];
__device__ float d_e[EA * NH];
__device__ int   d_deg[NN];
__device__ int   d_rowptr[NN + 1];
__device__ int   d_cursor[NN];
__device__ int   d_csrsrc[EA];
__device__ int   d_gstart[NGB + 1];
__device__ float d_pool[NGB * HIDD];
__device__ __nv_bfloat16 d_Acat[(size_t)NN * KCAT];           // h split, [N, 2304]
__device__ __nv_bfloat16 d_WcatT[(size_t)NL * HIDD * KCAT];   // W^T split, [L, 768n, 2304k]

// ---------------- CSR build ----------------
__global__ void k_zero_deg() {
    int i = blockIdx.x * 256 + threadIdx.x;
    if (i < NN) d_deg[i] = 0;
}

__global__ void k_hist(const int* __restrict__ ei) {
    int i = blockIdx.x * 256 + threadIdx.x;
    if (i >= EA) return;
    int dst = (i < EE) ? ei[EE + i] : (i - EE);
    atomicAdd(&d_deg[dst], 1);
}

__global__ void k_scan() {
    __shared__ int sdata[1024];
    __shared__ int carry;
    int tid = threadIdx.x;
    if (tid == 0) { carry = 0; d_rowptr[0] = 0; }
    __syncthreads();
    for (int base = 0; base < NN; base += 1024) {
        int i = base + tid;
        int v = (i < NN) ? d_deg[i] : 0;
        sdata[tid] = v;
        __syncthreads();
        for (int off = 1; off < 1024; off <<= 1) {
            int t = (tid >= off) ? sdata[tid - off] : 0;
            __syncthreads();
            sdata[tid] += t;
            __syncthreads();
        }
        int incl = sdata[tid] + carry;
        if (i < NN) d_rowptr[i + 1] = incl;
        __syncthreads();
        if (tid == 1023) carry = incl;
        __syncthreads();
    }
    for (int i = tid; i < NN; i += 1024) d_cursor[i] = d_rowptr[i];
}

__global__ void k_scatter(const int* __restrict__ ei) {
    int i = blockIdx.x * 256 + threadIdx.x;
    if (i >= EA) return;
    int src, dst;
    if (i < EE) { src = ei[i]; dst = ei[EE + i]; }
    else        { src = i - EE; dst = src; }
    int slot = atomicAdd(&d_cursor[dst], 1);
    d_csrsrc[slot] = src;
}

__global__ void k_gstart(const int* __restrict__ batch) {
    int n = blockIdx.x * 256 + threadIdx.x;
    if (n >= NN) return;
    int b = batch[n];
    if (n == 0) {
        for (int bb = 0; bb <= b; bb++) d_gstart[bb] = 0;
    } else {
        int pb = batch[n - 1];
        if (pb != b) for (int bb = pb + 1; bb <= b; bb++) d_gstart[bb] = n;
    }
    if (n == NN - 1) {
        for (int bb = b + 1; bb <= NGB; bb++) d_gstart[bb] = NN;
    }
}

// ---------------- helpers for split writes ----------------
__device__ __forceinline__ void write_split(int n, int k, float v) {
    __nv_bfloat16 hi = __float2bfloat16(v);
    __nv_bfloat16 lo = __float2bfloat16(v - __bfloat162float(hi));
    size_t base = (size_t)n * KCAT;
    d_Acat[base + k]            = hi;
    d_Acat[base + HIDD + k]     = lo;
    d_Acat[base + 2 * HIDD + k] = hi;
}

// ---------------- input projection (writes h AND its split) ----------------
__global__ void k_proj(const float* __restrict__ x, const float* __restrict__ W,
                       const float* __restrict__ b) {
    int id = blockIdx.x * 256 + threadIdx.x;
    if (id >= NN * HIDD) return;
    int n = id / HIDD, j = id % HIDD;
    float s = b[j];
#pragma unroll
    for (int f = 0; f < 5; f++) s += x[n * 5 + f] * W[f * HIDD + j];
    d_h[id] = s;
    write_split(n, j, s);
}

// ---------------- bf16 split: weights (once) ----------------
__global__ void k_split_w(const float* __restrict__ convW) {
    int id = blockIdx.x * 256 + threadIdx.x;
    if (id >= NL * HIDD * HIDD) return;
    int l = id / (HIDD * HIDD);
    int rem = id % (HIDD * HIDD);
    int k = rem / HIDD, n = rem % HIDD;
    float v = convW[id];
    __nv_bfloat16 hi = __float2bfloat16(v);
    __nv_bfloat16 lo = __float2bfloat16(v - __bfloat162float(hi));
    size_t base = ((size_t)l * HIDD + n) * KCAT;
    d_WcatT[base + k]            = hi;   // pairs with h_hi
    d_WcatT[base + HIDD + k]     = hi;   // pairs with h_lo
    d_WcatT[base + 2 * HIDD + k] = lo;   // pairs with h_hi
}

// =====================================================================
// HMMA GEMM: d_g[m,n] = sum_k Acat[m,k] * WcatT[l][n,k]
// block tile 128x256, BK=64, 3-stage cp.async, mma.sync.m16n8k16.bf16
// =====================================================================
#define BK 64
#define STAGES 3
#define STG_A 16384                       // 128 rows x 128 bytes
#define STG_B 32768                       // 256 rows x 128 bytes
#define SMEM_GEMM (STAGES * (STG_A + STG_B))   // 147456

__device__ __forceinline__ uint32_t swz(uint32_t b) { return b ^ ((b >> 3) & 0x70); }

__device__ __forceinline__ uint32_t smem_u32(const void* p) {
    uint32_t a;
    asm("{ .reg .u64 t; cvta.to.shared.u64 t, %1; cvt.u32.u64 %0, t; }" : "=r"(a) : "l"(p));
    return a;
}

#define CP_ASYNC(dst, src, sz) \
    asm volatile("cp.async.cg.shared.global [%0], [%1], 16, %2;" \
        :: "r"(dst), "l"(src), "r"(sz))
#define CP_COMMIT() asm volatile("cp.async.commit_group;")
#define CP_WAIT1()  asm volatile("cp.async.wait_group 1;")

#define LDMX4(r0, r1, r2, r3, a) \
    asm volatile("ldmatrix.sync.aligned.m8n8.x4.shared.b16 {%0,%1,%2,%3}, [%4];" \
        : "=r"(r0), "=r"(r1), "=r"(r2), "=r"(r3) : "r"(a))

#define MMA16816(d, a, b) \
    asm volatile("mma.sync.aligned.m16n8k16.row.col.f32.bf16.bf16.f32 " \
        "{%0,%1,%2,%3}, {%4,%5,%6,%7}, {%8,%9}, {%0,%1,%2,%3};" \
        : "+f"((d)[0]), "+f"((d)[1]), "+f"((d)[2]), "+f"((d)[3]) \
        : "r"((a)[0]), "r"((a)[1]), "r"((a)[2]), "r"((a)[3]), "r"((b)[0]), "r"((b)[1]))

__global__ __launch_bounds__(256, 1) void k_gemm_hmma(const __nv_bfloat16* __restrict__ Wl) {
    extern __shared__ __align__(128) char smem[];
    uint32_t sA = smem_u32(smem);                    // STAGES x 16KB
    uint32_t sB = sA + STAGES * STG_A;               // STAGES x 32KB

    const int tid = threadIdx.x;
    const int lane = tid & 31, warp = tid >> 5;
    const int wm = warp & 3, wn = warp >> 2;         // 4 m-warps x 2 n-warps
    const int mtile = blockIdx.y, ntile = blockIdx.x;
    const int mbase = mtile * 128;
    const int nbase = ntile * 256;

    const __nv_bfloat16* Ag = d_Acat;

    auto issue_stage = [&](int kt, int st) {
        int k0 = kt * BK;
        uint32_t a_dst = sA + st * STG_A;
#pragma unroll
        for (int it = 0; it < 4; it++) {             // A: 1024 chunks of 16B
            int id = it * 256 + tid;
            int row = id >> 3, ck = id & 7;
            int gr = mbase + row;
            const __nv_bfloat16* srcA = Ag + (size_t)gr * KCAT + k0 + ck * 8;
            CP_ASYNC(a_dst + swz(row * 128 + ck * 16), srcA, (gr < NN) ? 16 : 0);
        }
        uint32_t b_dst = sB + st * STG_B;
#pragma unroll
        for (int it = 0; it < 8; it++) {             // B: 2048 chunks of 16B
            int id = it * 256 + tid;
            int row = id >> 3, ck = id & 7;
            const __nv_bfloat16* srcB = Wl + (size_t)(nbase + row) * KCAT + k0 + ck * 8;
            CP_ASYNC(b_dst + swz(row * 128 + ck * 16), srcB, 16);
        }
        CP_COMMIT();
    };

    issue_stage(0, 0);
    issue_stage(1, 1);

    float acc[2][16][4];
#pragma unroll
    for (int i = 0; i < 2; i++)
#pragma unroll
        for (int j = 0; j < 16; j++)
#pragma unroll
            for (int c = 0; c < 4; c++) acc[i][j][c] = 0.f;

    const int NKT = KCAT / BK;   // 36
    for (int kt = 0; kt < NKT; kt++) {
        CP_WAIT1();
        __syncthreads();
        if (kt + 2 < NKT) issue_stage(kt + 2, (kt + 2) % STAGES);
        else CP_COMMIT();

        int st = kt % STAGES;
        uint32_t aS = sA + st * STG_A;
        uint32_t bS = sB + st * STG_B;

#pragma unroll
        for (int ks = 0; ks < 4; ks++) {             // k16 steps within BK
            uint32_t afr[2][4];
#pragma unroll
            for (int im = 0; im < 2; im++) {
                int row = wm * 32 + im * 16 + (lane & 15);
                int kk = ks * 16 + (lane >> 4) * 8;
                LDMX4(afr[im][0], afr[im][1], afr[im][2], afr[im][3],
                      aS + swz(row * 128 + kk * 2));
            }
            // two halves of 8 n8-frags each to cap register pressure
#pragma unroll
            for (int half = 0; half < 2; half++) {
                uint32_t bfr[8][2];
#pragma unroll
                for (int pr = 0; pr < 4; pr++) {
                    int nrow = wn * 128 + half * 64 + pr * 16 + (lane & 7) + ((lane & 16) ? 8 : 0);
                    int kk = ks * 16 + ((lane & 8) ? 8 : 0);
                    uint32_t r0, r1, r2, r3;
                    LDMX4(r0, r1, r2, r3, bS + swz(nrow * 128 + kk * 2));
                    bfr[pr * 2][0] = r0;     bfr[pr * 2][1] = r1;
                    bfr[pr * 2 + 1][0] = r2; bfr[pr * 2 + 1][1] = r3;
                }
#pragma unroll
                for (int im = 0; im < 2; im++)
#pragma unroll
                    for (int jn = 0; jn < 8; jn++)
                        MMA16816(acc[im][half * 8 + jn], afr[im], bfr[jn]);
            }
        }
        __syncthreads();
    }

    // epilogue
#pragma unroll
    for (int im = 0; im < 2; im++) {
        int r0 = mbase + wm * 32 + im * 16 + (lane >> 2);
#pragma unroll
        for (int jn = 0; jn < 16; jn++) {
            int col = nbase + wn * 128 + jn * 8 + (lane & 3) * 2;
            if (r0 < NN)
                *(float2*)&d_g[(size_t)r0 * HIDD + col] = make_float2(acc[im][jn][0], acc[im][jn][1]);
            if (r0 + 8 < NN)
                *(float2*)&d_g[(size_t)(r0 + 8) * HIDD + col] = make_float2(acc[im][jn][2], acc[im][jn][3]);
        }
    }
}

// ---------------- attention coefficients ----------------
__global__ void k_asd(const float* __restrict__ att_s, const float* __restrict__ att_d) {
    int id = blockIdx.x * 256 + threadIdx.x;
    if (id >= NN * NH) return;
    int h = id & 7;
    const float* gr = d_g + (size_t)(id >> 3) * HIDD + h * NC;
    const float* vs = att_s + h * NC;
    const float* vd = att_d + h * NC;
    float s1 = 0.f, s2 = 0.f;
#pragma unroll 8
    for (int c = 0; c < NC; c++) {
        float gv = gr[c];
        s1 += gv * vs[c];
        s2 += gv * vd[c];
    }
    d_as[id] = s1;
    d_ad[id] = s2;
}

// ---------------- per-node softmax + aggregate (+ split write) ----------------
__global__ __launch_bounds__(256) void k_attn(const float* __restrict__ bias) {
    int warp = threadIdx.x >> 5, lane = threadIdx.x & 31;
    int n = blockIdx.x * 8 + warp;
    __shared__ float s_inv[8][8];
    __shared__ float s_alpha[8][8];

    int beg = d_rowptr[n], end = d_rowptr[n + 1];
    float ad[8];
#pragma unroll
    for (int h = 0; h < 8; h++) ad[h] = d_ad[n * 8 + h];

    float mx[8];
#pragma unroll
    for (int h = 0; h < 8; h++) mx[h] = -1e30f;
    for (int i0 = beg; i0 < end; i0 += 32) {
        int idx = i0 + lane;
        bool v = idx < end;
        int s = v ? d_csrsrc[idx] : 0;
#pragma unroll
        for (int h = 0; h < 8; h++) {
            float e = -1e30f;
            if (v) {
                e = d_as[s * 8 + h] + ad[h];
                e = e > 0.f ? e : 0.2f * e;
                d_e[(size_t)idx * 8 + h] = e;
            }
            mx[h] = fmaxf(mx[h], e);
        }
    }
#pragma unroll
    for (int h = 0; h < 8; h++)
        for (int off = 16; off; off >>= 1)
            mx[h] = fmaxf(mx[h], __shfl_xor_sync(0xffffffffu, mx[h], off));

    float sm[8];
#pragma unroll
    for (int h = 0; h < 8; h++) sm[h] = 0.f;
    for (int i0 = beg; i0 < end; i0 += 32) {
        int idx = i0 + lane;
        bool v = idx < end;
#pragma unroll
        for (int h = 0; h < 8; h++) {
            if (v) {
                float p = __expf(d_e[(size_t)idx * 8 + h] - mx[h]);
                d_e[(size_t)idx * 8 + h] = p;
                sm[h] += p;
            }
        }
    }
#pragma unroll
    for (int h = 0; h < 8; h++)
        for (int off = 16; off; off >>= 1)
            sm[h] += __shfl_xor_sync(0xffffffffu, sm[h], off);
    if (lane == 0) {
#pragma unroll
        for (int h = 0; h < 8; h++) s_inv[warp][h] = 1.f / (sm[h] + 1e-16f);
    }
    __syncwarp();

    float acc[24];
#pragma unroll
    for (int t = 0; t < 24; t++) acc[t] = 0.f;
    for (int idx = beg; idx < end; idx++) {
        int s = d_csrsrc[idx];
        if (lane < 8) s_alpha[warp][lane] = d_e[(size_t)idx * 8 + lane] * s_inv[warp][lane];
        __syncwarp();
        const float* grow = d_g + (size_t)s * HIDD;
#pragma unroll
        for (int t = 0; t < 24; t++) {
            int j = lane + 32 * t;
            acc[t] += s_alpha[warp][j / 96] * grow[j];
        }
        __syncwarp();
    }
#pragma unroll
    for (int t = 0; t < 24; t++) {
        int j = lane + 32 * t;
        float v = acc[t] + bias[j];
        v = v > 0.f ? v : 0.f;
        d_h[(size_t)n * HIDD + j] = v;
        write_split(n, j, v);
    }
}

// ---------------- pooling / fc ----------------
__global__ void k_pool() {
    int b = blockIdx.x;
    int j = blockIdx.y * 256 + threadIdx.x;
    int beg = d_gstart[b], end = d_gstart[b + 1];
    float s = 0.f;
    for (int n = beg; n < end; n++) s += d_h[(size_t)n * HIDD + j];
    float cnt = (float)(end - beg);
    d_pool[b * HIDD + j] = s / fmaxf(cnt, 1.0f);
}

__global__ void k_fc(const float* __restrict__ W, const float* __restrict__ b,
                     float* __restrict__ out) {
    int id = blockIdx.x * 256 + threadIdx.x;
    if (id >= NGB * EMB) return;
    int bb = id / EMB, k = id % EMB;
    float s = b[k];
    for (int j = 0; j < HIDD; j++) s += d_pool[bb * HIDD + j] * W[j * EMB + k];
    out[id] = s;
}

// ---------------- host launch ----------------
extern "C" void kernel_launch(void* const* d_in, const int* in_sizes, int n_in,
                              void* d_out, int out_size) {
    const float* x     = (const float*)d_in[0];
    const int*   ei    = (const int*)d_in[1];
    const int*   batch = (const int*)d_in[2];
    const float* projW = (const float*)d_in[3];
    const float* projb = (const float*)d_in[4];
    const float* convW = (const float*)d_in[5];
    const float* attS  = (const float*)d_in[6];
    const float* attD  = (const float*)d_in[7];
    const float* convb = (const float*)d_in[8];
    const float* fcW   = (const float*)d_in[9];
    const float* fcb   = (const float*)d_in[10];
    float* out = (float*)d_out;

    static bool attr_set = false;
    if (!attr_set) {
        cudaFuncSetAttribute(k_gemm_hmma, cudaFuncAttributeMaxDynamicSharedMemorySize, SMEM_GEMM);
        attr_set = true;
    }

    void* pW = nullptr;
    cudaGetSymbolAddress(&pW, d_WcatT);
    const __nv_bfloat16* Wcat = (const __nv_bfloat16*)pW;

    k_zero_deg<<<(NN + 255) / 256, 256>>>();
    k_hist<<<(EA + 255) / 256, 256>>>(ei);
    k_scan<<<1, 1024>>>();
    k_scatter<<<(EA + 255) / 256, 256>>>(ei);
    k_gstart<<<(NN + 255) / 256, 256>>>(batch);
    k_proj<<<(NN * HIDD + 255) / 256, 256>>>(x, projW, projb);
    k_split_w<<<(NL * HIDD * HIDD + 255) / 256, 256>>>(convW);

    for (int l = 0; l < NL; l++) {
        dim3 gg(HIDD / 256, (NN + 127) / 128);   // 3 x 157
        k_gemm_hmma<<<gg, 256, SMEM_GEMM>>>(Wcat + (size_t)l * HIDD * KCAT);
        k_asd<<<(NN * NH + 255) / 256, 256>>>(attS + l * HIDD, attD + l * HIDD);
        k_attn<<<NN / 8, 256>>>(convb + l * HIDD);
    }

    dim3 gp(NGB, 3);
    k_pool<<<gp, 256>>>();
    k_fc<<<(NGB * EMB + 255) / 256, 256>>>(fcW, fcb, out);
}

// round 6
// speedup vs baseline: 2.0442x; 1.2194x over previous
#include <cuda_runtime.h>
#include <cuda_bf16.h>
#include <cstdint>

#define NN 20000
#define EE 320000
#define EA 340000      // E + N self loops
#define HIDD 768
#define NH 8
#define NC 96
#define NL 16
#define NGB 16
#define EMB 512
#define KCAT 2304      // 3 * HIDD (bf16 split: hi*hi + lo*hi + hi*lo)
#define MAXD 64        // smem softmax path cap (fallback to global beyond)

// ---------------- scratch (device globals; no allocations) ----------------
__device__ float d_h[NN * HIDD];
__device__ float d_g[NN * HIDD];
__device__ float d_as[NN * NH];
__device__ float d_ad[NN * NH];
__device__ float d_e[EA * NH];          // fallback path only
__device__ int   d_deg[NN];
__device__ int   d_rowptr[NN + 1];
__device__ int   d_cursor[NN];
__device__ int   d_csrsrc[EA];
__device__ int   d_gstart[NGB + 1];
__device__ float d_pool[NGB * HIDD];
__device__ __nv_bfloat16 d_Acat[(size_t)NN * KCAT];           // h split, [N, 2304]
__device__ __nv_bfloat16 d_WcatT[(size_t)NL * HIDD * KCAT];   // W^T split, [L, 768n, 2304k]

// ---------------- CSR build ----------------
__global__ void k_zero_deg() {
    int i = blockIdx.x * 256 + threadIdx.x;
    if (i < NN) d_deg[i] = 0;
}

__global__ void k_hist(const int* __restrict__ ei) {
    int i = blockIdx.x * 256 + threadIdx.x;
    if (i >= EA) return;
    int dst = (i < EE) ? ei[EE + i] : (i - EE);
    atomicAdd(&d_deg[dst], 1);
}

__global__ void k_scan() {
    __shared__ int sdata[1024];
    __shared__ int carry;
    int tid = threadIdx.x;
    if (tid == 0) { carry = 0; d_rowptr[0] = 0; }
    __syncthreads();
    for (int base = 0; base < NN; base += 1024) {
        int i = base + tid;
        int v = (i < NN) ? d_deg[i] : 0;
        sdata[tid] = v;
        __syncthreads();
        for (int off = 1; off < 1024; off <<= 1) {
            int t = (tid >= off) ? sdata[tid - off] : 0;
            __syncthreads();
            sdata[tid] += t;
            __syncthreads();
        }
        int incl = sdata[tid] + carry;
        if (i < NN) d_rowptr[i + 1] = incl;
        __syncthreads();
        if (tid == 1023) carry = incl;
        __syncthreads();
    }
    for (int i = tid; i < NN; i += 1024) d_cursor[i] = d_rowptr[i];
}

__global__ void k_scatter(const int* __restrict__ ei) {
    int i = blockIdx.x * 256 + threadIdx.x;
    if (i >= EA) return;
    int src, dst;
    if (i < EE) { src = ei[i]; dst = ei[EE + i]; }
    else        { src = i - EE; dst = src; }
    int slot = atomicAdd(&d_cursor[dst], 1);
    d_csrsrc[slot] = src;
}

__global__ void k_gstart(const int* __restrict__ batch) {
    int n = blockIdx.x * 256 + threadIdx.x;
    if (n >= NN) return;
    int b = batch[n];
    if (n == 0) {
        for (int bb = 0; bb <= b; bb++) d_gstart[bb] = 0;
    } else {
        int pb = batch[n - 1];
        if (pb != b) for (int bb = pb + 1; bb <= b; bb++) d_gstart[bb] = n;
    }
    if (n == NN - 1) {
        for (int bb = b + 1; bb <= NGB; bb++) d_gstart[bb] = NN;
    }
}

// ---------------- split write helpers ----------------
__device__ __forceinline__ void write_split(int n, int k, float v) {
    __nv_bfloat16 hi = __float2bfloat16(v);
    __nv_bfloat16 lo = __float2bfloat16(v - __bfloat162float(hi));
    size_t base = (size_t)n * KCAT;
    d_Acat[base + k]            = hi;
    d_Acat[base + HIDD + k]     = lo;
    d_Acat[base + 2 * HIDD + k] = hi;
}

__device__ __forceinline__ void write_split4(int n, int j, float4 v) {
    float vv[4] = {v.x, v.y, v.z, v.w};
    __nv_bfloat162 hp[2], lp[2];
#pragma unroll
    for (int q = 0; q < 2; q++) {
        __nv_bfloat16 h0 = __float2bfloat16(vv[2 * q]);
        __nv_bfloat16 h1 = __float2bfloat16(vv[2 * q + 1]);
        __nv_bfloat16 l0 = __float2bfloat16(vv[2 * q]     - __bfloat162float(h0));
        __nv_bfloat16 l1 = __float2bfloat16(vv[2 * q + 1] - __bfloat162float(h1));
        hp[q] = __nv_bfloat162(h0, h1);
        lp[q] = __nv_bfloat162(l0, l1);
    }
    size_t base = (size_t)n * KCAT;
    __nv_bfloat162* p0 = (__nv_bfloat162*)&d_Acat[base + j];
    __nv_bfloat162* p1 = (__nv_bfloat162*)&d_Acat[base + HIDD + j];
    __nv_bfloat162* p2 = (__nv_bfloat162*)&d_Acat[base + 2 * HIDD + j];
    p0[0] = hp[0]; p0[1] = hp[1];
    p1[0] = lp[0]; p1[1] = lp[1];
    p2[0] = hp[0]; p2[1] = hp[1];
}

// ---------------- input projection (writes h AND its split) ----------------
__global__ void k_proj(const float* __restrict__ x, const float* __restrict__ W,
                       const float* __restrict__ b) {
    int id = blockIdx.x * 256 + threadIdx.x;
    if (id >= NN * HIDD) return;
    int n = id / HIDD, j = id % HIDD;
    float s = b[j];
#pragma unroll
    for (int f = 0; f < 5; f++) s += x[n * 5 + f] * W[f * HIDD + j];
    d_h[id] = s;
    write_split(n, j, s);
}

// ---------------- bf16 split: weights (once) ----------------
__global__ void k_split_w(const float* __restrict__ convW) {
    int id = blockIdx.x * 256 + threadIdx.x;
    if (id >= NL * HIDD * HIDD) return;
    int l = id / (HIDD * HIDD);
    int rem = id % (HIDD * HIDD);
    int k = rem / HIDD, n = rem % HIDD;
    float v = convW[id];
    __nv_bfloat16 hi = __float2bfloat16(v);
    __nv_bfloat16 lo = __float2bfloat16(v - __bfloat162float(hi));
    size_t base = ((size_t)l * HIDD + n) * KCAT;
    d_WcatT[base + k]            = hi;
    d_WcatT[base + HIDD + k]     = hi;
    d_WcatT[base + 2 * HIDD + k] = lo;
}

// =====================================================================
// HMMA GEMM: 128x256 tile, BK=64, 3-stage cp.async, mma.m16n8k16.bf16
// =====================================================================
#define BK 64
#define STAGES 3
#define STG_A 16384
#define STG_B 32768
#define SMEM_GEMM (STAGES * (STG_A + STG_B))   // 147456

__device__ __forceinline__ uint32_t swz(uint32_t b) { return b ^ ((b >> 3) & 0x70); }

__device__ __forceinline__ uint32_t smem_u32(const void* p) {
    uint32_t a;
    asm("{ .reg .u64 t; cvta.to.shared.u64 t, %1; cvt.u32.u64 %0, t; }" : "=r"(a) : "l"(p));
    return a;
}

#define CP_ASYNC(dst, src, sz) \
    asm volatile("cp.async.cg.shared.global [%0], [%1], 16, %2;" \
        :: "r"(dst), "l"(src), "r"(sz))
#define CP_COMMIT() asm volatile("cp.async.commit_group;")
#define CP_WAIT1()  asm volatile("cp.async.wait_group 1;")

#define LDMX4(r0, r1, r2, r3, a) \
    asm volatile("ldmatrix.sync.aligned.m8n8.x4.shared.b16 {%0,%1,%2,%3}, [%4];" \
        : "=r"(r0), "=r"(r1), "=r"(r2), "=r"(r3) : "r"(a))

#define MMA16816(d, a, b) \
    asm volatile("mma.sync.aligned.m16n8k16.row.col.f32.bf16.bf16.f32 " \
        "{%0,%1,%2,%3}, {%4,%5,%6,%7}, {%8,%9}, {%0,%1,%2,%3};" \
        : "+f"((d)[0]), "+f"((d)[1]), "+f"((d)[2]), "+f"((d)[3]) \
        : "r"((a)[0]), "r"((a)[1]), "r"((a)[2]), "r"((a)[3]), "r"((b)[0]), "r"((b)[1]))

__global__ __launch_bounds__(256, 1) void k_gemm_hmma(const __nv_bfloat16* __restrict__ Wl) {
    extern __shared__ __align__(128) char smem[];
    uint32_t sA = smem_u32(smem);
    uint32_t sB = sA + STAGES * STG_A;

    const int tid = threadIdx.x;
    const int lane = tid & 31, warp = tid >> 5;
    const int wm = warp & 3, wn = warp >> 2;
    const int mtile = blockIdx.y, ntile = blockIdx.x;
    const int mbase = mtile * 128;
    const int nbase = ntile * 256;

    const __nv_bfloat16* Ag = d_Acat;

    auto issue_stage = [&](int kt, int st) {
        int k0 = kt * BK;
        uint32_t a_dst = sA + st * STG_A;
#pragma unroll
        for (int it = 0; it < 4; it++) {
            int id = it * 256 + tid;
            int row = id >> 3, ck = id & 7;
            int gr = mbase + row;
            const __nv_bfloat16* srcA = Ag + (size_t)gr * KCAT + k0 + ck * 8;
            CP_ASYNC(a_dst + swz(row * 128 + ck * 16), srcA, (gr < NN) ? 16 : 0);
        }
        uint32_t b_dst = sB + st * STG_B;
#pragma unroll
        for (int it = 0; it < 8; it++) {
            int id = it * 256 + tid;
            int row = id >> 3, ck = id & 7;
            const __nv_bfloat16* srcB = Wl + (size_t)(nbase + row) * KCAT + k0 + ck * 8;
            CP_ASYNC(b_dst + swz(row * 128 + ck * 16), srcB, 16);
        }
        CP_COMMIT();
    };

    issue_stage(0, 0);
    issue_stage(1, 1);

    float acc[2][16][4];
#pragma unroll
    for (int i = 0; i < 2; i++)
#pragma unroll
        for (int j = 0; j < 16; j++)
#pragma unroll
            for (int c = 0; c < 4; c++) acc[i][j][c] = 0.f;

    const int NKT = KCAT / BK;
    for (int kt = 0; kt < NKT; kt++) {
        CP_WAIT1();
        __syncthreads();
        if (kt + 2 < NKT) issue_stage(kt + 2, (kt + 2) % STAGES);
        else CP_COMMIT();

        int st = kt % STAGES;
        uint32_t aS = sA + st * STG_A;
        uint32_t bS = sB + st * STG_B;

#pragma unroll
        for (int ks = 0; ks < 4; ks++) {
            uint32_t afr[2][4];
#pragma unroll
            for (int im = 0; im < 2; im++) {
                int row = wm * 32 + im * 16 + (lane & 15);
                int kk = ks * 16 + (lane >> 4) * 8;
                LDMX4(afr[im][0], afr[im][1], afr[im][2], afr[im][3],
                      aS + swz(row * 128 + kk * 2));
            }
#pragma unroll
            for (int half = 0; half < 2; half++) {
                uint32_t bfr[8][2];
#pragma unroll
                for (int pr = 0; pr < 4; pr++) {
                    int nrow = wn * 128 + half * 64 + pr * 16 + (lane & 7) + ((lane & 16) ? 8 : 0);
                    int kk = ks * 16 + ((lane & 8) ? 8 : 0);
                    uint32_t r0, r1, r2, r3;
                    LDMX4(r0, r1, r2, r3, bS + swz(nrow * 128 + kk * 2));
                    bfr[pr * 2][0] = r0;     bfr[pr * 2][1] = r1;
                    bfr[pr * 2 + 1][0] = r2; bfr[pr * 2 + 1][1] = r3;
                }
#pragma unroll
                for (int im = 0; im < 2; im++)
#pragma unroll
                    for (int jn = 0; jn < 8; jn++)
                        MMA16816(acc[im][half * 8 + jn], afr[im], bfr[jn]);
            }
        }
        __syncthreads();
    }

#pragma unroll
    for (int im = 0; im < 2; im++) {
        int r0 = mbase + wm * 32 + im * 16 + (lane >> 2);
#pragma unroll
        for (int jn = 0; jn < 16; jn++) {
            int col = nbase + wn * 128 + jn * 8 + (lane & 3) * 2;
            if (r0 < NN)
                *(float2*)&d_g[(size_t)r0 * HIDD + col] = make_float2(acc[im][jn][0], acc[im][jn][1]);
            if (r0 + 8 < NN)
                *(float2*)&d_g[(size_t)(r0 + 8) * HIDD + col] = make_float2(acc[im][jn][2], acc[im][jn][3]);
        }
    }
}

// ---------------- attention coefficients (float4) ----------------
__global__ void k_asd(const float* __restrict__ att_s, const float* __restrict__ att_d) {
    int id = blockIdx.x * 256 + threadIdx.x;
    if (id >= NN * NH) return;
    int h = id & 7;
    const float4* gr = (const float4*)(d_g + (size_t)(id >> 3) * HIDD + h * NC);
    const float4* vs = (const float4*)(att_s + h * NC);
    const float4* vd = (const float4*)(att_d + h * NC);
    float s1 = 0.f, s2 = 0.f;
#pragma unroll
    for (int c = 0; c < NC / 4; c++) {
        float4 gv = gr[c], a = vs[c], b = vd[c];
        s1 += gv.x * a.x + gv.y * a.y + gv.z * a.z + gv.w * a.w;
        s2 += gv.x * b.x + gv.y * b.y + gv.z * b.z + gv.w * b.w;
    }
    d_as[id] = s1;
    d_ad[id] = s2;
}

// ---------------- per-node softmax + aggregate (smem path + fallback) ----------------
__global__ __launch_bounds__(256) void k_attn(const float* __restrict__ bias) {
    __shared__ float ebuf[8][MAXD * 8];     // 16 KB: per-warp per-edge per-head
    __shared__ float s_alpha[8][8];         // fallback broadcast

    int warp = threadIdx.x >> 5, lane = threadIdx.x & 31;
    int n = blockIdx.x * 8 + warp;

    int beg = d_rowptr[n], end = d_rowptr[n + 1];
    int deg = end - beg;

    const float4* adp = (const float4*)(d_ad + n * 8);
    float4 ad0 = adp[0], ad1 = adp[1];
    float ad[8] = {ad0.x, ad0.y, ad0.z, ad0.w, ad1.x, ad1.y, ad1.z, ad1.w};

    float4 acc4[6];
#pragma unroll
    for (int t = 0; t < 6; t++) acc4[t] = make_float4(0.f, 0.f, 0.f, 0.f);

    int head_t[6];
#pragma unroll
    for (int t = 0; t < 6; t++) head_t[t] = (lane + 32 * t) / 24;   // = (4*(lane+32t))/96

    if (deg <= MAXD) {
        // ---- pass A: logits into smem, track max ----
        float mx[8];
#pragma unroll
        for (int h = 0; h < 8; h++) mx[h] = -1e30f;
#pragma unroll
        for (int it = 0; it < 2; it++) {
            int le = it * 32 + lane;
            if (le < deg) {
                int s = d_csrsrc[beg + le];
                const float4* ap = (const float4*)(d_as + s * 8);
                float4 a0 = ap[0], a1 = ap[1];
                float ev[8] = {a0.x, a0.y, a0.z, a0.w, a1.x, a1.y, a1.z, a1.w};
#pragma unroll
                for (int h = 0; h < 8; h++) {
                    float e = ev[h] + ad[h];
                    e = e > 0.f ? e : 0.2f * e;
                    ebuf[warp][le * 8 + h] = e;
                    mx[h] = fmaxf(mx[h], e);
                }
            }
        }
#pragma unroll
        for (int h = 0; h < 8; h++)
            for (int off = 16; off; off >>= 1)
                mx[h] = fmaxf(mx[h], __shfl_xor_sync(0xffffffffu, mx[h], off));
        __syncwarp();

        // ---- pass B: exp + sum ----
        float sm[8];
#pragma unroll
        for (int h = 0; h < 8; h++) sm[h] = 0.f;
#pragma unroll
        for (int it = 0; it < 2; it++) {
            int le = it * 32 + lane;
            if (le < deg) {
#pragma unroll
                for (int h = 0; h < 8; h++) {
                    float p = __expf(ebuf[warp][le * 8 + h] - mx[h]);
                    ebuf[warp][le * 8 + h] = p;
                    sm[h] += p;
                }
            }
        }
#pragma unroll
        for (int h = 0; h < 8; h++)
            for (int off = 16; off; off >>= 1)
                sm[h] += __shfl_xor_sync(0xffffffffu, sm[h], off);
        float inv[8];
#pragma unroll
        for (int h = 0; h < 8; h++) inv[h] = 1.f / (sm[h] + 1e-16f);
        __syncwarp();

        // ---- scale p -> alpha in place ----
#pragma unroll
        for (int it = 0; it < 2; it++) {
            int le = it * 32 + lane;
            if (le < deg) {
#pragma unroll
                for (int h = 0; h < 8; h++)
                    ebuf[warp][le * 8 + h] *= inv[h];
            }
        }
        __syncwarp();

        // ---- pass C: float4 gather, 2 edges per iter ----
        int le = 0;
        for (; le + 2 <= deg; le += 2) {
            int s0 = d_csrsrc[beg + le];
            int s1 = d_csrsrc[beg + le + 1];
            const float4* g0 = (const float4*)(d_g + (size_t)s0 * HIDD);
            const float4* g1 = (const float4*)(d_g + (size_t)s1 * HIDD);
#pragma unroll
            for (int t = 0; t < 6; t++) {
                int j4 = lane + 32 * t;
                float a0 = ebuf[warp][le * 8 + head_t[t]];
                float a1 = ebuf[warp][(le + 1) * 8 + head_t[t]];
                float4 v0 = g0[j4], v1 = g1[j4];
                acc4[t].x += a0 * v0.x + a1 * v1.x;
                acc4[t].y += a0 * v0.y + a1 * v1.y;
                acc4[t].z += a0 * v0.z + a1 * v1.z;
                acc4[t].w += a0 * v0.w + a1 * v1.w;
            }
        }
        if (le < deg) {
            int s0 = d_csrsrc[beg + le];
            const float4* g0 = (const float4*)(d_g + (size_t)s0 * HIDD);
#pragma unroll
            for (int t = 0; t < 6; t++) {
                int j4 = lane + 32 * t;
                float a0 = ebuf[warp][le * 8 + head_t[t]];
                float4 v0 = g0[j4];
                acc4[t].x += a0 * v0.x;
                acc4[t].y += a0 * v0.y;
                acc4[t].z += a0 * v0.z;
                acc4[t].w += a0 * v0.w;
            }
        }
    } else {
        // ---------- fallback: global d_e path (rare) ----------
        float mx[8];
#pragma unroll
        for (int h = 0; h < 8; h++) mx[h] = -1e30f;
        for (int i0 = beg; i0 < end; i0 += 32) {
            int idx = i0 + lane;
            bool v = idx < end;
            int s = v ? d_csrsrc[idx] : 0;
#pragma unroll
            for (int h = 0; h < 8; h++) {
                float e = -1e30f;
                if (v) {
                    e = d_as[s * 8 + h] + ad[h];
                    e = e > 0.f ? e : 0.2f * e;
                    d_e[(size_t)idx * 8 + h] = e;
                }
                mx[h] = fmaxf(mx[h], e);
            }
        }
#pragma unroll
        for (int h = 0; h < 8; h++)
            for (int off = 16; off; off >>= 1)
                mx[h] = fmaxf(mx[h], __shfl_xor_sync(0xffffffffu, mx[h], off));

        float sm[8];
#pragma unroll
        for (int h = 0; h < 8; h++) sm[h] = 0.f;
        for (int i0 = beg; i0 < end; i0 += 32) {
            int idx = i0 + lane;
            bool v = idx < end;
#pragma unroll
            for (int h = 0; h < 8; h++) {
                if (v) {
                    float p = __expf(d_e[(size_t)idx * 8 + h] - mx[h]);
                    d_e[(size_t)idx * 8 + h] = p;
                    sm[h] += p;
                }
            }
        }
#pragma unroll
        for (int h = 0; h < 8; h++)
            for (int off = 16; off; off >>= 1)
                sm[h] += __shfl_xor_sync(0xffffffffu, sm[h], off);
        if (lane == 0) {
#pragma unroll
            for (int h = 0; h < 8; h++) s_alpha[warp][h] = 1.f / (sm[h] + 1e-16f);
        }
        __syncwarp();
        float inv8 = s_alpha[warp][lane & 7];
        for (int idx = beg; idx < end; idx++) {
            int s = d_csrsrc[idx];
            if (lane < 8) s_alpha[warp][lane] = d_e[(size_t)idx * 8 + lane] * inv8;
            __syncwarp();
            const float4* g0 = (const float4*)(d_g + (size_t)s * HIDD);
#pragma unroll
            for (int t = 0; t < 6; t++) {
                int j4 = lane + 32 * t;
                float a0 = s_alpha[warp][head_t[t]];
                float4 v0 = g0[j4];
                acc4[t].x += a0 * v0.x;
                acc4[t].y += a0 * v0.y;
                acc4[t].z += a0 * v0.z;
                acc4[t].w += a0 * v0.w;
            }
            __syncwarp();
        }
    }

    // ---- epilogue: bias + relu, write h and split ----
#pragma unroll
    for (int t = 0; t < 6; t++) {
        int j = 4 * (lane + 32 * t);
        float4 b4 = *(const float4*)(bias + j);
        float4 v = acc4[t];
        v.x = fmaxf(v.x + b4.x, 0.f);
        v.y = fmaxf(v.y + b4.y, 0.f);
        v.z = fmaxf(v.z + b4.z, 0.f);
        v.w = fmaxf(v.w + b4.w, 0.f);
        *(float4*)&d_h[(size_t)n * HIDD + j] = v;
        write_split4(n, j, v);
    }
}

// ---------------- pooling / fc ----------------
__global__ void k_pool() {
    int b = blockIdx.x;
    int j = blockIdx.y * 256 + threadIdx.x;
    int beg = d_gstart[b], end = d_gstart[b + 1];
    float s = 0.f;
    for (int n = beg; n < end; n++) s += d_h[(size_t)n * HIDD + j];
    float cnt = (float)(end - beg);
    d_pool[b * HIDD + j] = s / fmaxf(cnt, 1.0f);
}

__global__ void k_fc(const float* __restrict__ W, const float* __restrict__ b,
                     float* __restrict__ out) {
    int id = blockIdx.x * 256 + threadIdx.x;
    if (id >= NGB * EMB) return;
    int bb = id / EMB, k = id % EMB;
    float s = b[k];
    for (int j = 0; j < HIDD; j++) s += d_pool[bb * HIDD + j] * W[j * EMB + k];
    out[id] = s;
}

// ---------------- host launch ----------------
extern "C" void kernel_launch(void* const* d_in, const int* in_sizes, int n_in,
                              void* d_out, int out_size) {
    const float* x     = (const float*)d_in[0];
    const int*   ei    = (const int*)d_in[1];
    const int*   batch = (const int*)d_in[2];
    const float* projW = (const float*)d_in[3];
    const float* projb = (const float*)d_in[4];
    const float* convW = (const float*)d_in[5];
    const float* attS  = (const float*)d_in[6];
    const float* attD  = (const float*)d_in[7];
    const float* convb = (const float*)d_in[8];
    const float* fcW   = (const float*)d_in[9];
    const float* fcb   = (const float*)d_in[10];
    float* out = (float*)d_out;

    static bool attr_set = false;
    if (!attr_set) {
        cudaFuncSetAttribute(k_gemm_hmma, cudaFuncAttributeMaxDynamicSharedMemorySize, SMEM_GEMM);
        attr_set = true;
    }

    void* pW = nullptr;
    cudaGetSymbolAddress(&pW, d_WcatT);
    const __nv_bfloat16* Wcat = (const __nv_bfloat16*)pW;

    k_zero_deg<<<(NN + 255) / 256, 256>>>();
    k_hist<<<(EA + 255) / 256, 256>>>(ei);
    k_scan<<<1, 1024>>>();
    k_scatter<<<(EA + 255) / 256, 256>>>(ei);
    k_gstart<<<(NN + 255) / 256, 256>>>(batch);
    k_proj<<<(NN * HIDD + 255) / 256, 256>>>(x, projW, projb);
    k_split_w<<<(NL * HIDD * HIDD + 255) / 256, 256>>>(convW);

    for (int l = 0; l < NL; l++) {
        dim3 gg(HIDD / 256, (NN + 127) / 128);   // 3 x 157
        k_gemm_hmma<<<gg, 256, SMEM_GEMM>>>(Wcat + (size_t)l * HIDD * KCAT);
        k_asd<<<(NN * NH + 255) / 256, 256>>>(attS + l * HIDD, attD + l * HIDD);
        k_attn<<<NN / 8, 256>>>(convb + l * HIDD);
    }

    dim3 gp(NGB, 3);
    k_pool<<<gp, 256>>>();
    k_fc<<<(NGB * EMB + 255) / 256, 256>>>(fcW, fcb, out);
}

// round 8
// speedup vs baseline: 2.3174x; 1.1336x over previous
#include <cuda_runtime.h>
#include <cuda_bf16.h>
#include <cstdint>

#define NN 20000
#define EE 320000
#define EA 340000      // E + N self loops
#define HIDD 768
#define NH 8
#define NC 96
#define NL 16
#define NGB 16
#define EMB 512
#define KCAT 2304      // 3 * HIDD (bf16 split: hi*hi + lo*hi + hi*lo)
#define MAXD 64        // smem softmax path cap (fallback to global beyond)

// ---------------- scratch (device globals; no allocations) ----------------
__device__ float d_h[NN * HIDD];
__device__ float d_g[NN * HIDD];
__device__ float d_as[NN * NH];
__device__ float d_ad[NN * NH];
__device__ float d_e[EA * NH];          // fallback path only
__device__ int   d_deg[NN];
__device__ int   d_rowptr[NN + 1];
__device__ int   d_cursor[NN];
__device__ int   d_csrsrc[EA];
__device__ int   d_gstart[NGB + 1];
__device__ float d_pool[NGB * HIDD];
__device__ __nv_bfloat16 d_Acat[(size_t)NN * KCAT];           // h split, [N, 2304]
__device__ __nv_bfloat16 d_WcatT[(size_t)NL * HIDD * KCAT];   // W^T split, [L, 768n, 2304k]

// ---------------- CSR build ----------------
__global__ void k_zero_deg() {
    int i = blockIdx.x * 256 + threadIdx.x;
    if (i < NN) d_deg[i] = 0;
}

__global__ void k_hist(const int* __restrict__ ei) {
    int i = blockIdx.x * 256 + threadIdx.x;
    if (i >= EA) return;
    int dst = (i < EE) ? ei[EE + i] : (i - EE);
    atomicAdd(&d_deg[dst], 1);
}

__global__ void k_scan() {
    __shared__ int sdata[1024];
    __shared__ int carry;
    int tid = threadIdx.x;
    if (tid == 0) { carry = 0; d_rowptr[0] = 0; }
    __syncthreads();
    for (int base = 0; base < NN; base += 1024) {
        int i = base + tid;
        int v = (i < NN) ? d_deg[i] : 0;
        sdata[tid] = v;
        __syncthreads();
        for (int off = 1; off < 1024; off <<= 1) {
            int t = (tid >= off) ? sdata[tid - off] : 0;
            __syncthreads();
            sdata[tid] += t;
            __syncthreads();
        }
        int incl = sdata[tid] + carry;
        if (i < NN) d_rowptr[i + 1] = incl;
        __syncthreads();
        if (tid == 1023) carry = incl;
        __syncthreads();
    }
    for (int i = tid; i < NN; i += 1024) d_cursor[i] = d_rowptr[i];
}

__global__ void k_scatter(const int* __restrict__ ei) {
    int i = blockIdx.x * 256 + threadIdx.x;
    if (i >= EA) return;
    int src, dst;
    if (i < EE) { src = ei[i]; dst = ei[EE + i]; }
    else        { src = i - EE; dst = src; }
    int slot = atomicAdd(&d_cursor[dst], 1);
    d_csrsrc[slot] = src;
}

__global__ void k_gstart(const int* __restrict__ batch) {
    int n = blockIdx.x * 256 + threadIdx.x;
    if (n >= NN) return;
    int b = batch[n];
    if (n == 0) {
        for (int bb = 0; bb <= b; bb++) d_gstart[bb] = 0;
    } else {
        int pb = batch[n - 1];
        if (pb != b) for (int bb = pb + 1; bb <= b; bb++) d_gstart[bb] = n;
    }
    if (n == NN - 1) {
        for (int bb = b + 1; bb <= NGB; bb++) d_gstart[bb] = NN;
    }
}

__global__ void k_zero_asd() {
    int i = blockIdx.x * 256 + threadIdx.x;
    if (i < NN * NH) { d_as[i] = 0.f; d_ad[i] = 0.f; }
}

// ---------------- split write helpers ----------------
__device__ __forceinline__ void write_split(int n, int k, float v) {
    __nv_bfloat16 hi = __float2bfloat16(v);
    __nv_bfloat16 lo = __float2bfloat16(v - __bfloat162float(hi));
    size_t base = (size_t)n * KCAT;
    d_Acat[base + k]            = hi;
    d_Acat[base + HIDD + k]     = lo;
    d_Acat[base + 2 * HIDD + k] = hi;
}

__device__ __forceinline__ void write_split4(int n, int j, float4 v) {
    float vv[4] = {v.x, v.y, v.z, v.w};
    __nv_bfloat162 hp[2], lp[2];
#pragma unroll
    for (int q = 0; q < 2; q++) {
        __nv_bfloat16 h0 = __float2bfloat16(vv[2 * q]);
        __nv_bfloat16 h1 = __float2bfloat16(vv[2 * q + 1]);
        __nv_bfloat16 l0 = __float2bfloat16(vv[2 * q]     - __bfloat162float(h0));
        __nv_bfloat16 l1 = __float2bfloat16(vv[2 * q + 1] - __bfloat162float(h1));
        hp[q] = __nv_bfloat162(h0, h1);
        lp[q] = __nv_bfloat162(l0, l1);
    }
    size_t base = (size_t)n * KCAT;
    __nv_bfloat162* p0 = (__nv_bfloat162*)&d_Acat[base + j];
    __nv_bfloat162* p1 = (__nv_bfloat162*)&d_Acat[base + HIDD + j];
    __nv_bfloat162* p2 = (__nv_bfloat162*)&d_Acat[base + 2 * HIDD + j];
    p0[0] = hp[0]; p0[1] = hp[1];
    p1[0] = lp[0]; p1[1] = lp[1];
    p2[0] = hp[0]; p2[1] = hp[1];
}

// ---------------- input projection (split only; d_h not needed here) ----------------
__global__ void k_proj(const float* __restrict__ x, const float* __restrict__ W,
                       const float* __restrict__ b) {
    int id = blockIdx.x * 256 + threadIdx.x;
    if (id >= NN * HIDD) return;
    int n = id / HIDD, j = id % HIDD;
    float s = b[j];
#pragma unroll
    for (int f = 0; f < 5; f++) s += x[n * 5 + f] * W[f * HIDD + j];
    write_split(n, j, s);
}

// ---------------- bf16 split: weights (once) ----------------
__global__ void k_split_w(const float* __restrict__ convW) {
    int id = blockIdx.x * 256 + threadIdx.x;
    if (id >= NL * HIDD * HIDD) return;
    int l = id / (HIDD * HIDD);
    int rem = id % (HIDD * HIDD);
    int k = rem / HIDD, n = rem % HIDD;
    float v = convW[id];
    __nv_bfloat16 hi = __float2bfloat16(v);
    __nv_bfloat16 lo = __float2bfloat16(v - __bfloat162float(hi));
    size_t base = ((size_t)l * HIDD + n) * KCAT;
    d_WcatT[base + k]            = hi;
    d_WcatT[base + HIDD + k]     = hi;
    d_WcatT[base + 2 * HIDD + k] = lo;
}

// =====================================================================
// HMMA GEMM: 128x256 tile, BK=64, 4-stage cp.async, mma.m16n8k16.bf16
// Fused epilogue: d_g store + att_src/att_dst dot products (atomicAdd)
// =====================================================================
#define BK 64
#define STAGES 4
#define STG_A 16384
#define STG_B 32768
#define SMEM_GEMM (STAGES * (STG_A + STG_B))   // 196608

__device__ __forceinline__ uint32_t swz(uint32_t b) { return b ^ ((b >> 3) & 0x70); }

__device__ __forceinline__ uint32_t smem_u32(const void* p) {
    uint32_t a;
    asm("{ .reg .u64 t; cvta.to.shared.u64 t, %1; cvt.u32.u64 %0, t; }" : "=r"(a) : "l"(p));
    return a;
}

#define CP_ASYNC(dst, src, sz) \
    asm volatile("cp.async.cg.shared.global [%0], [%1], 16, %2;" \
        :: "r"(dst), "l"(src), "r"(sz))
#define CP_COMMIT() asm volatile("cp.async.commit_group;")
#define CP_WAIT2()  asm volatile("cp.async.wait_group 2;")

#define LDMX4(r0, r1, r2, r3, a) \
    asm volatile("ldmatrix.sync.aligned.m8n8.x4.shared.b16 {%0,%1,%2,%3}, [%4];" \
        : "=r"(r0), "=r"(r1), "=r"(r2), "=r"(r3) : "r"(a))

#define MMA16816(d, a, b) \
    asm volatile("mma.sync.aligned.m16n8k16.row.col.f32.bf16.bf16.f32 " \
        "{%0,%1,%2,%3}, {%4,%5,%6,%7}, {%8,%9}, {%0,%1,%2,%3};" \
        : "+f"((d)[0]), "+f"((d)[1]), "+f"((d)[2]), "+f"((d)[3]) \
        : "r"((a)[0]), "r"((a)[1]), "r"((a)[2]), "r"((a)[3]), "r"((b)[0]), "r"((b)[1]))

__global__ __launch_bounds__(256, 1) void k_gemm_hmma(
    const __nv_bfloat16* __restrict__ Wl,
    const float* __restrict__ attS, const float* __restrict__ attD)
{
    extern __shared__ __align__(128) char smem[];
    uint32_t sA = smem_u32(smem);
    uint32_t sB = sA + STAGES * STG_A;

    const int tid = threadIdx.x;
    const int lane = tid & 31, warp = tid >> 5;
    const int wm = warp & 3, wn = warp >> 2;
    const int mtile = blockIdx.y, ntile = blockIdx.x;
    const int mbase = mtile * 128;
    const int nbase = ntile * 256;

    const __nv_bfloat16* Ag = d_Acat;

    auto issue_stage = [&](int kt, int st) {
        int k0 = kt * BK;
        uint32_t a_dst = sA + st * STG_A;
#pragma unroll
        for (int it = 0; it < 4; it++) {
            int id = it * 256 + tid;
            int row = id >> 3, ck = id & 7;
            int gr = mbase + row;
            const __nv_bfloat16* srcA = Ag + (size_t)gr * KCAT + k0 + ck * 8;
            CP_ASYNC(a_dst + swz(row * 128 + ck * 16), srcA, (gr < NN) ? 16 : 0);
        }
        uint32_t b_dst = sB + st * STG_B;
#pragma unroll
        for (int it = 0; it < 8; it++) {
            int id = it * 256 + tid;
            int row = id >> 3, ck = id & 7;
            const __nv_bfloat16* srcB = Wl + (size_t)(nbase + row) * KCAT + k0 + ck * 8;
            CP_ASYNC(b_dst + swz(row * 128 + ck * 16), srcB, 16);
        }
        CP_COMMIT();
    };

    issue_stage(0, 0);
    issue_stage(1, 1);
    issue_stage(2, 2);

    float acc[2][16][4];
#pragma unroll
    for (int i = 0; i < 2; i++)
#pragma unroll
        for (int j = 0; j < 16; j++)
#pragma unroll
            for (int c = 0; c < 4; c++) acc[i][j][c] = 0.f;

    const int NKT = KCAT / BK;
    for (int kt = 0; kt < NKT; kt++) {
        CP_WAIT2();
        __syncthreads();
        if (kt + 3 < NKT) issue_stage(kt + 3, (kt + 3) % STAGES);
        else CP_COMMIT();

        int st = kt % STAGES;
        uint32_t aS = sA + st * STG_A;
        uint32_t bS = sB + st * STG_B;

#pragma unroll
        for (int ks = 0; ks < 4; ks++) {
            uint32_t afr[2][4];
#pragma unroll
            for (int im = 0; im < 2; im++) {
                int row = wm * 32 + im * 16 + (lane & 15);
                int kk = ks * 16 + (lane >> 4) * 8;
                LDMX4(afr[im][0], afr[im][1], afr[im][2], afr[im][3],
                      aS + swz(row * 128 + kk * 2));
            }
#pragma unroll
            for (int half = 0; half < 2; half++) {
                uint32_t bfr[8][2];
#pragma unroll
                for (int pr = 0; pr < 4; pr++) {
                    int nrow = wn * 128 + half * 64 + pr * 16 + (lane & 7) + ((lane & 16) ? 8 : 0);
                    int kk = ks * 16 + ((lane & 8) ? 8 : 0);
                    uint32_t r0, r1, r2, r3;
                    LDMX4(r0, r1, r2, r3, bS + swz(nrow * 128 + kk * 2));
                    bfr[pr * 2][0] = r0;     bfr[pr * 2][1] = r1;
                    bfr[pr * 2 + 1][0] = r2; bfr[pr * 2 + 1][1] = r3;
                }
#pragma unroll
                for (int im = 0; im < 2; im++)
#pragma unroll
                    for (int jn = 0; jn < 8; jn++)
                        MMA16816(acc[im][half * 8 + jn], afr[im], bfr[jn]);
            }
        }
        __syncthreads();
    }

    // ---------------- fused epilogue ----------------
    const int base0 = nbase + wn * 128;
    const int hA = base0 / 96;          // head of first col; cols span heads hA..hA+1
    float ps[2][2][2];                  // [im][rowhalf][slot] for att_src
    float pd[2][2][2];
#pragma unroll
    for (int a = 0; a < 2; a++)
#pragma unroll
        for (int b = 0; b < 2; b++)
#pragma unroll
            for (int c = 0; c < 2; c++) { ps[a][b][c] = 0.f; pd[a][b][c] = 0.f; }

#pragma unroll
    for (int jn = 0; jn < 16; jn++) {
        int col = base0 + jn * 8 + (lane & 3) * 2;
        int slot = (col / 96) - hA;     // 0 or 1 (col even -> col,col+1 same head)
        float as0 = __ldg(attS + col), as1 = __ldg(attS + col + 1);
        float ad0 = __ldg(attD + col), ad1 = __ldg(attD + col + 1);
#pragma unroll
        for (int im = 0; im < 2; im++) {
            int r0 = mbase + wm * 32 + im * 16 + (lane >> 2);
            if (r0 < NN)
                *(float2*)&d_g[(size_t)r0 * HIDD + col] =
                    make_float2(acc[im][jn][0], acc[im][jn][1]);
            if (r0 + 8 < NN)
                *(float2*)&d_g[(size_t)(r0 + 8) * HIDD + col] =
                    make_float2(acc[im][jn][2], acc[im][jn][3]);
            ps[im][0][slot] += acc[im][jn][0] * as0 + acc[im][jn][1] * as1;
            pd[im][0][slot] += acc[im][jn][0] * ad0 + acc[im][jn][1] * ad1;
            ps[im][1][slot] += acc[im][jn][2] * as0 + acc[im][jn][3] * as1;
            pd[im][1][slot] += acc[im][jn][2] * ad0 + acc[im][jn][3] * ad1;
        }
    }
    // reduce over the 4 lanes sharing a row (lane&3 group), then atomicAdd
#pragma unroll
    for (int im = 0; im < 2; im++)
#pragma unroll
        for (int rh = 0; rh < 2; rh++)
#pragma unroll
            for (int sl = 0; sl < 2; sl++) {
                float vs = ps[im][rh][sl], vd = pd[im][rh][sl];
                vs += __shfl_xor_sync(0xffffffffu, vs, 1);
                vs += __shfl_xor_sync(0xffffffffu, vs, 2);
                vd += __shfl_xor_sync(0xffffffffu, vd, 1);
                vd += __shfl_xor_sync(0xffffffffu, vd, 2);
                if ((lane & 3) == 0) {
                    int row = mbase + wm * 32 + im * 16 + (lane >> 2) + rh * 8;
                    int h = hA + sl;
                    if (row < NN && h < NH) {
                        atomicAdd(&d_as[row * 8 + h], vs);
                        atomicAdd(&d_ad[row * 8 + h], vd);
                    }
                }
            }
}

// ---------------- per-node softmax + aggregate (smem path + fallback) ----------------
__global__ __launch_bounds__(256) void k_attn(const float* __restrict__ bias, int write_h) {
    __shared__ float ebuf[8][MAXD * 8];
    __shared__ float s_alpha[8][8];

    int warp = threadIdx.x >> 5, lane = threadIdx.x & 31;
    int n = blockIdx.x * 8 + warp;

    int beg = d_rowptr[n], end = d_rowptr[n + 1];
    int deg = end - beg;

    const float4* adp = (const float4*)(d_ad + n * 8);
    float4 ad0 = adp[0], ad1 = adp[1];
    float ad[8] = {ad0.x, ad0.y, ad0.z, ad0.w, ad1.x, ad1.y, ad1.z, ad1.w};

    float4 acc4[6];
#pragma unroll
    for (int t = 0; t < 6; t++) acc4[t] = make_float4(0.f, 0.f, 0.f, 0.f);

    int head_t[6];
#pragma unroll
    for (int t = 0; t < 6; t++) head_t[t] = (lane + 32 * t) / 24;

    if (deg <= MAXD) {
        float mx[8];
#pragma unroll
        for (int h = 0; h < 8; h++) mx[h] = -1e30f;
#pragma unroll
        for (int it = 0; it < 2; it++) {
            int le = it * 32 + lane;
            if (le < deg) {
                int s = d_csrsrc[beg + le];
                const float4* ap = (const float4*)(d_as + s * 8);
                float4 a0 = ap[0], a1 = ap[1];
                float ev[8] = {a0.x, a0.y, a0.z, a0.w, a1.x, a1.y, a1.z, a1.w};
#pragma unroll
                for (int h = 0; h < 8; h++) {
                    float e = ev[h] + ad[h];
                    e = e > 0.f ? e : 0.2f * e;
                    ebuf[warp][le * 8 + h] = e;
                    mx[h] = fmaxf(mx[h], e);
                }
            }
        }
#pragma unroll
        for (int h = 0; h < 8; h++)
            for (int off = 16; off; off >>= 1)
                mx[h] = fmaxf(mx[h], __shfl_xor_sync(0xffffffffu, mx[h], off));
        __syncwarp();

        float sm[8];
#pragma unroll
        for (int h = 0; h < 8; h++) sm[h] = 0.f;
#pragma unroll
        for (int it = 0; it < 2; it++) {
            int le = it * 32 + lane;
            if (le < deg) {
#pragma unroll
                for (int h = 0; h < 8; h++) {
                    float p = __expf(ebuf[warp][le * 8 + h] - mx[h]);
                    ebuf[warp][le * 8 + h] = p;
                    sm[h] += p;
                }
            }
        }
#pragma unroll
        for (int h = 0; h < 8; h++)
            for (int off = 16; off; off >>= 1)
                sm[h] += __shfl_xor_sync(0xffffffffu, sm[h], off);
        float inv[8];
#pragma unroll
        for (int h = 0; h < 8; h++) inv[h] = 1.f / (sm[h] + 1e-16f);
        __syncwarp();

#pragma unroll
        for (int it = 0; it < 2; it++) {
            int le = it * 32 + lane;
            if (le < deg) {
#pragma unroll
                for (int h = 0; h < 8; h++)
                    ebuf[warp][le * 8 + h] *= inv[h];
            }
        }
        __syncwarp();

        int le = 0;
        for (; le + 2 <= deg; le += 2) {
            int s0 = d_csrsrc[beg + le];
            int s1 = d_csrsrc[beg + le + 1];
            const float4* g0 = (const float4*)(d_g + (size_t)s0 * HIDD);
            const float4* g1 = (const float4*)(d_g + (size_t)s1 * HIDD);
#pragma unroll
            for (int t = 0; t < 6; t++) {
                int j4 = lane + 32 * t;
                float a0 = ebuf[warp][le * 8 + head_t[t]];
                float a1 = ebuf[warp][(le + 1) * 8 + head_t[t]];
                float4 v0 = g0[j4], v1 = g1[j4];
                acc4[t].x += a0 * v0.x + a1 * v1.x;
                acc4[t].y += a0 * v0.y + a1 * v1.y;
                acc4[t].z += a0 * v0.z + a1 * v1.z;
                acc4[t].w += a0 * v0.w + a1 * v1.w;
            }
        }
        if (le < deg) {
            int s0 = d_csrsrc[beg + le];
            const float4* g0 = (const float4*)(d_g + (size_t)s0 * HIDD);
#pragma unroll
            for (int t = 0; t < 6; t++) {
                int j4 = lane + 32 * t;
                float a0 = ebuf[warp][le * 8 + head_t[t]];
                float4 v0 = g0[j4];
                acc4[t].x += a0 * v0.x;
                acc4[t].y += a0 * v0.y;
                acc4[t].z += a0 * v0.z;
                acc4[t].w += a0 * v0.w;
            }
        }
    } else {
        float mx[8];
#pragma unroll
        for (int h = 0; h < 8; h++) mx[h] = -1e30f;
        for (int i0 = beg; i0 < end; i0 += 32) {
            int idx = i0 + lane;
            bool v = idx < end;
            int s = v ? d_csrsrc[idx] : 0;
#pragma unroll
            for (int h = 0; h < 8; h++) {
                float e = -1e30f;
                if (v) {
                    e = d_as[s * 8 + h] + ad[h];
                    e = e > 0.f ? e : 0.2f * e;
                    d_e[(size_t)idx * 8 + h] = e;
                }
                mx[h] = fmaxf(mx[h], e);
            }
        }
#pragma unroll
        for (int h = 0; h < 8; h++)
            for (int off = 16; off; off >>= 1)
                mx[h] = fmaxf(mx[h], __shfl_xor_sync(0xffffffffu, mx[h], off));

        float sm[8];
#pragma unroll
        for (int h = 0; h < 8; h++) sm[h] = 0.f;
        for (int i0 = beg; i0 < end; i0 += 32) {
            int idx = i0 + lane;
            bool v = idx < end;
#pragma unroll
            for (int h = 0; h < 8; h++) {
                if (v) {
                    float p = __expf(d_e[(size_t)idx * 8 + h] - mx[h]);
                    d_e[(size_t)idx * 8 + h] = p;
                    sm[h] += p;
                }
            }
        }
#pragma unroll
        for (int h = 0; h < 8; h++)
            for (int off = 16; off; off >>= 1)
                sm[h] += __shfl_xor_sync(0xffffffffu, sm[h], off);
        if (lane == 0) {
#pragma unroll
            for (int h = 0; h < 8; h++) s_alpha[warp][h] = 1.f / (sm[h] + 1e-16f);
        }
        __syncwarp();
        float inv8 = s_alpha[warp][lane & 7];
        for (int idx = beg; idx < end; idx++) {
            int s = d_csrsrc[idx];
            if (lane < 8) s_alpha[warp][lane] = d_e[(size_t)idx * 8 + lane] * inv8;
            __syncwarp();
            const float4* g0 = (const float4*)(d_g + (size_t)s * HIDD);
#pragma unroll
            for (int t = 0; t < 6; t++) {
                int j4 = lane + 32 * t;
                float a0 = s_alpha[warp][head_t[t]];
                float4 v0 = g0[j4];
                acc4[t].x += a0 * v0.x;
                acc4[t].y += a0 * v0.y;
                acc4[t].z += a0 * v0.z;
                acc4[t].w += a0 * v0.w;
            }
            __syncwarp();
        }
    }

#pragma unroll
    for (int t = 0; t < 6; t++) {
        int j = 4 * (lane + 32 * t);
        float4 b4 = *(const float4*)(bias + j);
        float4 v = acc4[t];
        v.x = fmaxf(v.x + b4.x, 0.f);
        v.y = fmaxf(v.y + b4.y, 0.f);
        v.z = fmaxf(v.z + b4.z, 0.f);
        v.w = fmaxf(v.w + b4.w, 0.f);
        if (write_h) *(float4*)&d_h[(size_t)n * HIDD + j] = v;
        write_split4(n, j, v);
    }
}

// ---------------- pooling / fc ----------------
__global__ void k_pool() {
    int b = blockIdx.x;
    int j = blockIdx.y * 256 + threadIdx.x;
    int beg = d_gstart[b], end = d_gstart[b + 1];
    float s = 0.f;
    for (int n = beg; n < end; n++) s += d_h[(size_t)n * HIDD + j];
    float cnt = (float)(end - beg);
    d_pool[b * HIDD + j] = s / fmaxf(cnt, 1.0f);
}

__global__ void k_fc(const float* __restrict__ W, const float* __restrict__ b,
                     float* __restrict__ out) {
    int id = blockIdx.x * 256 + threadIdx.x;
    if (id >= NGB * EMB) return;
    int bb = id / EMB, k = id % EMB;
    float s = b[k];
    for (int j = 0; j < HIDD; j++) s += d_pool[bb * HIDD + j] * W[j * EMB + k];
    out[id] = s;
}

// ---------------- host launch ----------------
extern "C" void kernel_launch(void* const* d_in, const int* in_sizes, int n_in,
                              void* d_out, int out_size) {
    const float* x     = (const float*)d_in[0];
    const int*   ei    = (const int*)d_in[1];
    const int*   batch = (const int*)d_in[2];
    const float* projW = (const float*)d_in[3];
    const float* projb = (const float*)d_in[4];
    const float* convW = (const float*)d_in[5];
    const float* attS  = (const float*)d_in[6];
    const float* attD  = (const float*)d_in[7];
    const float* convb = (const float*)d_in[8];
    const float* fcW   = (const float*)d_in[9];
    const float* fcb   = (const float*)d_in[10];
    float* out = (float*)d_out;

    static bool attr_set = false;
    if (!attr_set) {
        cudaFuncSetAttribute(k_gemm_hmma, cudaFuncAttributeMaxDynamicSharedMemorySize, SMEM_GEMM);
        attr_set = true;
    }

    void* pW = nullptr;
    cudaGetSymbolAddress(&pW, d_WcatT);
    const __nv_bfloat16* Wcat = (const __nv_bfloat16*)pW;

    k_zero_deg<<<(NN + 255) / 256, 256>>>();
    k_hist<<<(EA + 255) / 256, 256>>>(ei);
    k_scan<<<1, 1024>>>();
    k_scatter<<<(EA + 255) / 256, 256>>>(ei);
    k_gstart<<<(NN + 255) / 256, 256>>>(batch);
    k_proj<<<(NN * HIDD + 255) / 256, 256>>>(x, projW, projb);
    k_split_w<<<(NL * HIDD * HIDD + 255) / 256, 256>>>(convW);
    k_zero_asd<<<(NN * NH + 255) / 256, 256>>>();

    for (int l = 0; l < NL; l++) {
        dim3 gg(HIDD / 256, (NN + 127) / 128);   // 3 x 157
        k_gemm_hmma<<<gg, 256, SMEM_GEMM>>>(Wcat + (size_t)l * HIDD * KCAT,
                                            attS + l * HIDD, attD + l * HIDD);
        k_attn<<<NN / 8, 256>>>(convb + l * HIDD, (l == NL - 1) ? 1 : 0);
        if (l != NL - 1) k_zero_asd<<<(NN * NH + 255) / 256, 256>>>();
    }

    dim3 gp(NGB, 3);
    k_pool<<<gp, 256>>>();
    k_fc<<<(NGB * EMB + 255) / 256, 256>>>(fcW, fcb, out);
}